// round 6
// baseline (speedup 1.0000x reference)
#include <cuda_runtime.h>
#include <cuda_bf16.h>
#include <cstdint>

#define BATCH 512
#define NODES 128
#define NFEAT 256
#define KTOT  32768          // NODES*NFEAT
#define SPLITS 32
#define KSLICE 1024          // KTOT/SPLITS
#define SEC   (BATCH*NFEAT)  // 131072

// ---------------------------------------------------------------------------
// Scratch (__device__ globals; allocation is forbidden)
// ---------------------------------------------------------------------------
__device__ __nv_bfloat16 g_gwT_hi[NFEAT * NFEAT];                   // [g][f]
__device__ __nv_bfloat16 g_gwT_lo[NFEAT * NFEAT];
__device__ __nv_bfloat16 g_x_hi[(size_t)BATCH * NODES * NFEAT];     // [b][node][f]
__device__ __nv_bfloat16 g_x_lo[(size_t)BATCH * NODES * NFEAT];
__device__ __nv_bfloat16 g_adj_hi[(size_t)BATCH * NODES * NODES];   // [b][n][m]
__device__ __nv_bfloat16 g_adj_lo[(size_t)BATCH * NODES * NODES];
__device__ __nv_bfloat16 g_fcw_hi[(size_t)NFEAT * KTOT];            // [o][k]
__device__ __nv_bfloat16 g_fcw_lo[(size_t)NFEAT * KTOT];
__device__ __nv_bfloat16 g_supT_hi[(size_t)BATCH * NFEAT * NODES];  // [b][g][node]
__device__ __nv_bfloat16 g_supT_lo[(size_t)BATCH * NFEAT * NODES];
__device__ __nv_bfloat16 g_mid_hi[(size_t)BATCH * NODES * NFEAT];   // [b][node][g]
__device__ __nv_bfloat16 g_mid_lo[(size_t)BATCH * NODES * NFEAT];
__device__ float         g_partial[(size_t)SPLITS * BATCH * NFEAT];

// ---------------------------------------------------------------------------
#define SW128(o) ((o) ^ (((o) >> 3) & 0x70))

__device__ __forceinline__ uint32_t smem_u32(const void* p) {
    uint32_t a;
    asm("{ .reg .u64 t; cvta.to.shared.u64 t, %1; cvt.u32.u64 %0, t; }"
        : "=r"(a) : "l"(p));
    return a;
}
__device__ __forceinline__ void split1(float v, __nv_bfloat16& h, __nv_bfloat16& l) {
    h = __float2bfloat16(v);
    l = __float2bfloat16(v - __bfloat162float(h));
}
__device__ __forceinline__ uint32_t pack2(__nv_bfloat16 a, __nv_bfloat16 b) {
    __nv_bfloat162 t = __halves2bfloat162(a, b);
    return *reinterpret_cast<uint32_t*>(&t);
}

// ---------------------------------------------------------------------------
// cp.async (base PTX, sm_80+)
// ---------------------------------------------------------------------------
__device__ __forceinline__ void cpa16(uint32_t s, const void* g) {
    asm volatile("cp.async.cg.shared.global [%0], [%1], 16;" :: "r"(s), "l"(g));
}
#define CP_COMMIT()  asm volatile("cp.async.commit_group;" ::: "memory")
#define CP_WAIT1()   asm volatile("cp.async.wait_group 1;" ::: "memory")
#define CP_WAIT0()   asm volatile("cp.async.wait_group 0;" ::: "memory")

// ---------------------------------------------------------------------------
// warp-MMA primitives (base PTX)
// ---------------------------------------------------------------------------
__device__ __forceinline__ void ldsm_x4(uint32_t addr, uint32_t* r) {
    asm volatile("ldmatrix.sync.aligned.m8n8.x4.shared.b16 {%0,%1,%2,%3}, [%4];"
        : "=r"(r[0]), "=r"(r[1]), "=r"(r[2]), "=r"(r[3]) : "r"(addr));
}
__device__ __forceinline__ void mma_bf16(float* c, const uint32_t* a, const uint32_t* b) {
    asm volatile(
        "mma.sync.aligned.m16n8k16.row.col.f32.bf16.bf16.f32 "
        "{%0,%1,%2,%3}, {%4,%5,%6,%7}, {%8,%9}, {%0,%1,%2,%3};"
        : "+f"(c[0]), "+f"(c[1]), "+f"(c[2]), "+f"(c[3])
        : "r"(a[0]), "r"(a[1]), "r"(a[2]), "r"(a[3]), "r"(b[0]), "r"(b[1]));
}
// A frags for m64: 4 x ldsm_x4 (lanes 0-15 rows, lanes 16-31 k-half)
__device__ __forceinline__ void load_a64(uint32_t tbase, int m0w, int kb,
                                         int lane, uint32_t* a) {
    const int kpart = ((lane >> 4) << 4);
    #pragma unroll
    for (int i = 0; i < 4; i++) {
        int row = m0w + 16 * i + (lane & 15);
        ldsm_x4(tbase + SW128(row * 128 + kb + kpart), a + 4 * i);
    }
}
// B frags for n32 (4 n8-tiles) in 2 ldsm_x4:
// lanes: bit4 -> which n8 of the pair, bit3 -> k-half, bits0-2 -> row
__device__ __forceinline__ void load_b32(uint32_t tbase, int n0, int kb,
                                         int lane, uint32_t* b) {
    const int kpart = (((lane >> 3) & 1) << 4);
    const int tofs  = ((lane >> 4) & 1) * 8;
    int row = n0 + tofs + (lane & 7);
    ldsm_x4(tbase + SW128(row * 128 + kb + kpart),        b);      // tiles 0,1
    ldsm_x4(tbase + SW128((row + 16) * 128 + kb + kpart), b + 4);  // tiles 2,3
}

// ---------------------------------------------------------------------------
// Uniform pipelined GEMM, warp tile 64x64, CTA tile (WR*64)x(WC*64), WR*WC=8
// C = A[M,K] * B[N,K]^T, all operands bf16 hi/lo pairs, 3-term emulation.
// MODE 1 (WR4,WC2): A=gwT, B=x_b      -> supT pairs        (ldc=NODES)
// MODE 2 (WR2,WC4): A=adj_b, B=supT_b -> mid pairs + bias  (ldc=NFEAT)
// MODE 3 (WR2,WC4): A=mid, B=fcw      -> partial fp32      (ldc=NFEAT)
// ---------------------------------------------------------------------------
template <int MODE, int WR, int WC>
__global__ void __launch_bounds__(256, 1)
gemm_p(const __nv_bfloat16* __restrict__ Ahi, const __nv_bfloat16* __restrict__ Alo, long sA,
       const __nv_bfloat16* __restrict__ Bhi, const __nv_bfloat16* __restrict__ Blo, long sB,
       const float* __restrict__ bias,
       float* __restrict__ outF, __nv_bfloat16* __restrict__ outHi,
       __nv_bfloat16* __restrict__ outLo, int nkt)
{
    constexpr int AROWS = WR * 64;
    constexpr int BROWS = WC * 64;
    constexpr int OFF_ALO = AROWS * 128;
    constexpr int OFF_BHI = 2 * AROWS * 128;
    constexpr int OFF_BLO = OFF_BHI + BROWS * 128;
    constexpr int STAGE   = OFF_BLO + BROWS * 128;   // 96 KB

    extern __shared__ char smraw[];
    char* sm = (char*)(((uintptr_t)smraw + 1023) & ~(uintptr_t)1023);
    const uint32_t sb = smem_u32(sm);

    const int tid  = threadIdx.x;
    const int lane = tid & 31;
    const int w    = tid >> 5;
    const int m0w  = (w / WC) * 64;
    const int n0w  = (w % WC) * 64;

    int ldc = 0;
    if constexpr (MODE == 1) {
        long b = blockIdx.x;
        Bhi += b * (long)(NODES * NFEAT);  Blo += b * (long)(NODES * NFEAT);
        outHi += b * (long)(NFEAT * NODES);
        outLo += b * (long)(NFEAT * NODES);
        ldc = NODES;
    } else if constexpr (MODE == 2) {
        long b = blockIdx.x;
        Ahi += b * (long)(NODES * NODES);  Alo += b * (long)(NODES * NODES);
        Bhi += b * (long)(NFEAT * NODES);  Blo += b * (long)(NFEAT * NODES);
        outHi += b * (long)(NODES * NFEAT);
        outLo += b * (long)(NODES * NFEAT);
        ldc = NFEAT;
    } else {
        long split = blockIdx.x, mb = blockIdx.y;
        Ahi += (mb * 128) * (long)KTOT + split * KSLICE;
        Alo += (mb * 128) * (long)KTOT + split * KSLICE;
        Bhi += split * KSLICE;
        Blo += split * KSLICE;
        outF += split * (long)SEC + (mb * 128) * (long)NFEAT;
        ldc = NFEAT;
    }

    // stage loader
    auto stage_load = [&](int stage, int kt) {
        const uint32_t base = sb + stage * STAGE;
        const int k0 = kt * 64;
        #pragma unroll
        for (int it = 0; it < 2 * WR; it++) {          // A: AROWS*8 chunks
            int idx = tid + it * 256;
            int row = idx >> 3, c = idx & 7;
            uint32_t so = SW128(row * 128 + c * 16);
            long ga = (long)row * sA + k0 + c * 8;
            cpa16(base + so,           Ahi + ga);
            cpa16(base + OFF_ALO + so, Alo + ga);
        }
        #pragma unroll
        for (int it = 0; it < 2 * WC; it++) {          // B: BROWS*8 chunks
            int idx = tid + it * 256;
            int row = idx >> 3, c = idx & 7;
            uint32_t so = SW128(row * 128 + c * 16);
            long gb = (long)row * sB + k0 + c * 8;
            cpa16(base + OFF_BHI + so, Bhi + gb);
            cpa16(base + OFF_BLO + so, Blo + gb);
        }
    };

    float acc[128];
    #pragma unroll
    for (int i = 0; i < 128; i++) acc[i] = 0.f;

    stage_load(0, 0); CP_COMMIT();
    if (nkt > 1) stage_load(1, 1);
    CP_COMMIT();

    for (int kt = 0; kt < nkt; kt++) {
        const int st = kt & 1;
        if (kt + 1 < nkt) CP_WAIT1(); else CP_WAIT0();
        __syncthreads();

        const uint32_t base = sb + st * STAGE;
        #pragma unroll
        for (int ks = 0; ks < 4; ks++) {
            const int kb = ks * 32;
            uint32_t ah[16], al[16];
            load_a64(base,           m0w, kb, lane, ah);
            load_a64(base + OFF_ALO, m0w, kb, lane, al);
            #pragma unroll
            for (int h = 0; h < 2; h++) {              // n32 halves
                const int n0h = n0w + h * 32;
                uint32_t bh[8], bl[8];
                load_b32(base + OFF_BHI, n0h, kb, lane, bh);
                load_b32(base + OFF_BLO, n0h, kb, lane, bl);
                #pragma unroll
                for (int i = 0; i < 4; i++) {
                    #pragma unroll
                    for (int j = 0; j < 4; j++) {
                        const int jj = h * 4 + j;
                        float* c = acc + (i * 8 + jj) * 4;
                        const uint32_t* bhj = bh + 4 * (j >> 1) + 2 * (j & 1);
                        const uint32_t* blj = bl + 4 * (j >> 1) + 2 * (j & 1);
                        mma_bf16(c, ah + 4 * i, bhj);  // hi*hi
                        mma_bf16(c, ah + 4 * i, blj);  // hi*lo
                        mma_bf16(c, al + 4 * i, bhj);  // lo*hi
                    }
                }
            }
        }
        __syncthreads();
        if (kt + 2 < nkt) { stage_load(st, kt + 2); }
        CP_COMMIT();
    }

    // ---- epilogue ----
    #pragma unroll
    for (int i = 0; i < 4; i++) {
        #pragma unroll
        for (int jj = 0; jj < 8; jj++) {
            const float* c = acc + (i * 8 + jj) * 4;
            int r0 = m0w + 16 * i + (lane >> 2);
            int c0 = n0w + 8 * jj + 2 * (lane & 3);
            if constexpr (MODE == 3) {
                *(float2*)&outF[(long)r0 * ldc + c0]       = make_float2(c[0], c[1]);
                *(float2*)&outF[(long)(r0 + 8) * ldc + c0] = make_float2(c[2], c[3]);
            } else {
                float v0 = c[0], v1 = c[1], v2 = c[2], v3 = c[3];
                if constexpr (MODE == 2) {
                    float b0 = __ldg(&bias[c0]), b1 = __ldg(&bias[c0 + 1]);
                    v0 += b0; v1 += b1; v2 += b0; v3 += b1;
                }
                __nv_bfloat16 h0, l0, h1, l1;
                split1(v0, h0, l0); split1(v1, h1, l1);
                long o0 = (long)r0 * ldc + c0;
                *(uint32_t*)&outHi[o0] = pack2(h0, h1);
                *(uint32_t*)&outLo[o0] = pack2(l0, l1);
                split1(v2, h0, l0); split1(v3, h1, l1);
                long o1 = (long)(r0 + 8) * ldc + c0;
                *(uint32_t*)&outHi[o1] = pack2(h0, h1);
                *(uint32_t*)&outLo[o1] = pack2(l0, l1);
            }
        }
    }
}

#define SMEM_BYTES (2 * 98304 + 1024)

// ---------------------------------------------------------------------------
// prep kernels
// ---------------------------------------------------------------------------
__global__ void __launch_bounds__(256)
split_arr(const float* __restrict__ src, __nv_bfloat16* __restrict__ hi,
          __nv_bfloat16* __restrict__ lo, long n4)
{
    long i = (long)blockIdx.x * 256 + threadIdx.x;
    if (i >= n4) return;
    float4 v = ((const float4*)src)[i];
    __nv_bfloat16 h0, h1, h2, h3, l0, l1, l2, l3;
    split1(v.x, h0, l0); split1(v.y, h1, l1);
    split1(v.z, h2, l2); split1(v.w, h3, l3);
    ((uint2*)hi)[i] = make_uint2(pack2(h0, h1), pack2(h2, h3));
    ((uint2*)lo)[i] = make_uint2(pack2(l0, l1), pack2(l2, l3));
}

__global__ void __launch_bounds__(256)
prep_w(const float* __restrict__ wsrc, __nv_bfloat16* __restrict__ hi,
       __nv_bfloat16* __restrict__ lo)
{
    int g = blockIdx.x, f = threadIdx.x;
    float v = wsrc[(long)f * NFEAT + g];
    __nv_bfloat16 h, l; split1(v, h, l);
    hi[(long)g * NFEAT + f] = h;
    lo[(long)g * NFEAT + f] = l;
}

// ---------------------------------------------------------------------------
// finalize: reduce split-K partials + fc_b, write 3 output sections
// ---------------------------------------------------------------------------
__global__ void __launch_bounds__(256)
finalize(const float* __restrict__ P, const float* __restrict__ fc_b,
         const float* __restrict__ x, float* __restrict__ out)
{
    const int idx = blockIdx.x * blockDim.x + threadIdx.x;
    if (idx >= SEC) return;
    const int b = idx >> 8;
    const int f = idx & 255;
    float v = fc_b[f];
    #pragma unroll
    for (int s = 0; s < SPLITS; s++)
        v += P[(long)s * SEC + idx];
    out[idx]           = v;
    out[2 * SEC + idx] = v;
    out[SEC + idx]     = x[(long)b * KTOT + f];   // x[b,0,f]
}

// ---------------------------------------------------------------------------
extern "C" void kernel_launch(void* const* d_in, const int* in_sizes, int n_in,
                              void* d_out, int out_size)
{
    const float* x     = (const float*)d_in[0];
    const float* adj   = (const float*)d_in[1];
    const float* gcn_w = (const float*)d_in[2];
    const float* gcn_b = (const float*)d_in[3];
    const float* fc_w  = (const float*)d_in[4];
    const float* fc_b  = (const float*)d_in[5];
    float* out = (float*)d_out;

    __nv_bfloat16 *gwT_hi, *gwT_lo, *x_hi, *x_lo, *adj_hi, *adj_lo;
    __nv_bfloat16 *fcw_hi, *fcw_lo, *supT_hi, *supT_lo, *mid_hi, *mid_lo;
    float* partial;
    cudaGetSymbolAddress((void**)&gwT_hi,  g_gwT_hi);
    cudaGetSymbolAddress((void**)&gwT_lo,  g_gwT_lo);
    cudaGetSymbolAddress((void**)&x_hi,    g_x_hi);
    cudaGetSymbolAddress((void**)&x_lo,    g_x_lo);
    cudaGetSymbolAddress((void**)&adj_hi,  g_adj_hi);
    cudaGetSymbolAddress((void**)&adj_lo,  g_adj_lo);
    cudaGetSymbolAddress((void**)&fcw_hi,  g_fcw_hi);
    cudaGetSymbolAddress((void**)&fcw_lo,  g_fcw_lo);
    cudaGetSymbolAddress((void**)&supT_hi, g_supT_hi);
    cudaGetSymbolAddress((void**)&supT_lo, g_supT_lo);
    cudaGetSymbolAddress((void**)&mid_hi,  g_mid_hi);
    cudaGetSymbolAddress((void**)&mid_lo,  g_mid_lo);
    cudaGetSymbolAddress((void**)&partial, g_partial);

    cudaFuncSetAttribute(gemm_p<1,4,2>, cudaFuncAttributeMaxDynamicSharedMemorySize, SMEM_BYTES);
    cudaFuncSetAttribute(gemm_p<2,2,4>, cudaFuncAttributeMaxDynamicSharedMemorySize, SMEM_BYTES);
    cudaFuncSetAttribute(gemm_p<3,2,4>, cudaFuncAttributeMaxDynamicSharedMemorySize, SMEM_BYTES);

    // 0) preps
    prep_w<<<NFEAT, NFEAT>>>(gcn_w, gwT_hi, gwT_lo);
    {
        long n4 = (long)BATCH * NODES * NFEAT / 4;        // x
        split_arr<<<(unsigned)((n4 + 255) / 256), 256>>>(x, x_hi, x_lo, n4);
    }
    {
        long n4 = (long)BATCH * NODES * NODES / 4;        // adj
        split_arr<<<(unsigned)((n4 + 255) / 256), 256>>>(adj, adj_hi, adj_lo, n4);
    }
    {
        long n4 = (long)NFEAT * KTOT / 4;                 // fc_w
        split_arr<<<(unsigned)((n4 + 255) / 256), 256>>>(fc_w, fcw_hi, fcw_lo, n4);
    }

    // 1) supT[b][g][node] = sum_f gwT[g][f] * x_b[node][f]   (M=256, N=128, K=256)
    gemm_p<1,4,2><<<BATCH, 256, SMEM_BYTES>>>(
        gwT_hi, gwT_lo, NFEAT, x_hi, x_lo, NFEAT,
        nullptr, nullptr, supT_hi, supT_lo, 4);

    // 2) mid[b][node][g] = sum_k adj_b[node][k]*supT_b[g][k] + gcn_b[g]  (M=128, N=256, K=128)
    gemm_p<2,2,4><<<BATCH, 256, SMEM_BYTES>>>(
        adj_hi, adj_lo, NODES, supT_hi, supT_lo, NODES,
        gcn_b, nullptr, mid_hi, mid_lo, 2);

    // 3) partial[s][m][n] = sum_{k in slice} mid[m][k]*fcw[n][k]  (M=512, N=256, K=1024/split)
    {
        dim3 grid(SPLITS, BATCH / 128);
        gemm_p<3,2,4><<<grid, 256, SMEM_BYTES>>>(
            mid_hi, mid_lo, KTOT, fcw_hi, fcw_lo, KTOT,
            nullptr, partial, nullptr, nullptr, KSLICE / 64);
    }
    // 4) reduce + bias + output sections
    finalize<<<SEC / 256, 256>>>(partial, fc_b, x, out);
}

// round 7
// speedup vs baseline: 1.1442x; 1.1442x over previous
#include <cuda_runtime.h>
#include <cuda_bf16.h>
#include <cuda_fp16.h>
#include <cstdint>

#define BATCH 512
#define NODES 128
#define NFEAT 256
#define KTOT  32768          // NODES*NFEAT
#define SPLITS 16
#define KSLICE 2048          // KTOT/SPLITS
#define SEC   (BATCH*NFEAT)  // 131072

// ---------------------------------------------------------------------------
// Scratch (__device__ globals; allocation is forbidden)
// ---------------------------------------------------------------------------
__device__ __nv_bfloat16 g_gwT_hi[NFEAT * NFEAT];                   // [g][f]
__device__ __nv_bfloat16 g_gwT_lo[NFEAT * NFEAT];
__device__ __nv_bfloat16 g_x_hi[(size_t)BATCH * NODES * NFEAT];     // [b][node][f]
__device__ __nv_bfloat16 g_x_lo[(size_t)BATCH * NODES * NFEAT];
__device__ __nv_bfloat16 g_adj_hi[(size_t)BATCH * NODES * NODES];   // [b][n][m]
__device__ __nv_bfloat16 g_adj_lo[(size_t)BATCH * NODES * NODES];
__device__ __half        g_fcw_h[(size_t)NFEAT * KTOT];             // [o][k] single fp16
__device__ __nv_bfloat16 g_supT_hi[(size_t)BATCH * NFEAT * NODES];  // [b][g][node]
__device__ __nv_bfloat16 g_supT_lo[(size_t)BATCH * NFEAT * NODES];
__device__ __half        g_mid_hi[(size_t)BATCH * NODES * NFEAT];   // [b][node][g] fp16 pair
__device__ __half        g_mid_lo[(size_t)BATCH * NODES * NFEAT];
__device__ float         g_partial[(size_t)SPLITS * BATCH * NFEAT];

// ---------------------------------------------------------------------------
#define SW128(o) ((o) ^ (((o) >> 3) & 0x70))

__device__ __forceinline__ uint32_t smem_u32(const void* p) {
    uint32_t a;
    asm("{ .reg .u64 t; cvta.to.shared.u64 t, %1; cvt.u32.u64 %0, t; }"
        : "=r"(a) : "l"(p));
    return a;
}
__device__ __forceinline__ void split1(float v, __nv_bfloat16& h, __nv_bfloat16& l) {
    h = __float2bfloat16(v);
    l = __float2bfloat16(v - __bfloat162float(h));
}
__device__ __forceinline__ uint32_t pack2(__nv_bfloat16 a, __nv_bfloat16 b) {
    __nv_bfloat162 t = __halves2bfloat162(a, b);
    return *reinterpret_cast<uint32_t*>(&t);
}
__device__ __forceinline__ void split1h(float v, __half& h, __half& l) {
    h = __float2half_rn(v);
    l = __float2half_rn(v - __half2float(h));
}
__device__ __forceinline__ uint32_t pack2h(__half a, __half b) {
    __half2 t = __halves2half2(a, b);
    return *reinterpret_cast<uint32_t*>(&t);
}

// ---------------------------------------------------------------------------
// cp.async (base PTX, sm_80+)
// ---------------------------------------------------------------------------
__device__ __forceinline__ void cpa16(uint32_t s, const void* g) {
    asm volatile("cp.async.cg.shared.global [%0], [%1], 16;" :: "r"(s), "l"(g));
}
#define CP_COMMIT()  asm volatile("cp.async.commit_group;" ::: "memory")
#define CP_WAIT1()   asm volatile("cp.async.wait_group 1;" ::: "memory")
#define CP_WAIT0()   asm volatile("cp.async.wait_group 0;" ::: "memory")

// ---------------------------------------------------------------------------
// warp-MMA primitives (base PTX)
// ---------------------------------------------------------------------------
__device__ __forceinline__ void ldsm_x4(uint32_t addr, uint32_t* r) {
    asm volatile("ldmatrix.sync.aligned.m8n8.x4.shared.b16 {%0,%1,%2,%3}, [%4];"
        : "=r"(r[0]), "=r"(r[1]), "=r"(r[2]), "=r"(r[3]) : "r"(addr));
}
__device__ __forceinline__ void ldsm_x2(uint32_t addr, uint32_t* r) {
    asm volatile("ldmatrix.sync.aligned.m8n8.x2.shared.b16 {%0,%1}, [%2];"
        : "=r"(r[0]), "=r"(r[1]) : "r"(addr));
}
__device__ __forceinline__ void mma_bf16(float* c, const uint32_t* a, const uint32_t* b) {
    asm volatile(
        "mma.sync.aligned.m16n8k16.row.col.f32.bf16.bf16.f32 "
        "{%0,%1,%2,%3}, {%4,%5,%6,%7}, {%8,%9}, {%0,%1,%2,%3};"
        : "+f"(c[0]), "+f"(c[1]), "+f"(c[2]), "+f"(c[3])
        : "r"(a[0]), "r"(a[1]), "r"(a[2]), "r"(a[3]), "r"(b[0]), "r"(b[1]));
}
__device__ __forceinline__ void mma_f16(float* c, const uint32_t* a, const uint32_t* b) {
    asm volatile(
        "mma.sync.aligned.m16n8k16.row.col.f32.f16.f16.f32 "
        "{%0,%1,%2,%3}, {%4,%5,%6,%7}, {%8,%9}, {%0,%1,%2,%3};"
        : "+f"(c[0]), "+f"(c[1]), "+f"(c[2]), "+f"(c[3])
        : "r"(a[0]), "r"(a[1]), "r"(a[2]), "r"(a[3]), "r"(b[0]), "r"(b[1]));
}
// A frags, m64: 4 x ldsm_x4
__device__ __forceinline__ void load_afrags(uint32_t tbase, int m0w, int kb,
                                            int lane, uint32_t* a) {
    const int kpart = ((lane >> 4) << 4);
    #pragma unroll
    for (int i = 0; i < 4; i++) {
        int row = m0w + 16 * i + (lane & 15);
        ldsm_x4(tbase + SW128(row * 128 + kb + kpart), a + 4 * i);
    }
}
// B frags, n32 (4 n8-tiles) via ldsm_x2
__device__ __forceinline__ void load_bfrags(uint32_t tbase, int n0w, int kb,
                                            int lane, uint32_t* b) {
    const int kpart = (((lane >> 3) & 1) << 4);
    #pragma unroll
    for (int j = 0; j < 4; j++) {
        int row = n0w + 8 * j + (lane & 7);
        ldsm_x2(tbase + SW128(row * 128 + kb + kpart), b + 2 * j);
    }
}
// B frags, n32 in 2 ldsm_x4 (verified correct in R6):
// regs: [t0klo,t0khi,t1klo,t1khi, t2klo,t2khi,t3klo,t3khi]; tile j at b+4*(j>>1)+2*(j&1)
__device__ __forceinline__ void load_b32(uint32_t tbase, int n0, int kb,
                                         int lane, uint32_t* b) {
    const int kpart = (((lane >> 3) & 1) << 4);
    const int tofs  = ((lane >> 4) & 1) * 8;
    int row = n0 + tofs + (lane & 7);
    ldsm_x4(tbase + SW128(row * 128 + kb + kpart),        b);
    ldsm_x4(tbase + SW128((row + 16) * 128 + kb + kpart), b + 4);
}

// ---------------------------------------------------------------------------
// gemm_p (R5 proven): 3-term bf16, CTA 128x128, warp 64x32, 3-stage pipeline
// MODE 1: A=gwT pair, B=x_b pair       -> supT bf16 pair   (ldc=NODES)
// MODE 2: A=adj_b pair, B=supT_b pair  -> mid fp16 pair + bias (ldc=NFEAT)
// ---------------------------------------------------------------------------
#define OFF_ALO 16384
#define OFF_BHI 32768
#define OFF_BLO 49152
#define STAGE_STRIDE 65536
#define NSTAGE 3
#define SMEM_BYTES (NSTAGE * STAGE_STRIDE + 1024)

template <int MODE>
__global__ void __launch_bounds__(256, 1)
gemm_p(const __nv_bfloat16* __restrict__ Ahi, const __nv_bfloat16* __restrict__ Alo, long sA,
       const __nv_bfloat16* __restrict__ Bhi, const __nv_bfloat16* __restrict__ Blo, long sB,
       const float* __restrict__ bias,
       void* __restrict__ outHiV, void* __restrict__ outLoV, int nkt)
{
    extern __shared__ char smraw[];
    char* sm = (char*)(((uintptr_t)smraw + 1023) & ~(uintptr_t)1023);
    const uint32_t sb = smem_u32(sm);

    const int tid  = threadIdx.x;
    const int lane = tid & 31;
    const int w    = tid >> 5;
    const int m0w  = (w >> 2) * 64;
    const int n0w  = (w & 3) * 32;

    int ldc = 0, coloff = 0;
    long outOfs = 0;
    if constexpr (MODE == 1) {
        long b = blockIdx.x, mh = blockIdx.y;
        Ahi += mh * 128 * NFEAT;  Alo += mh * 128 * NFEAT;
        Bhi += b * (long)(NODES * NFEAT);  Blo += b * (long)(NODES * NFEAT);
        outOfs = b * (long)(NFEAT * NODES) + mh * 128 * NODES;
        ldc = NODES;
    } else {
        long b = blockIdx.x, nh = blockIdx.y;
        Ahi += b * (long)(NODES * NODES);  Alo += b * (long)(NODES * NODES);
        Bhi += b * (long)(NFEAT * NODES) + nh * 128 * NODES;
        Blo += b * (long)(NFEAT * NODES) + nh * 128 * NODES;
        outOfs = b * (long)(NODES * NFEAT);
        bias += nh * 128;
        ldc = NFEAT; coloff = (int)nh * 128;
    }

    auto stage_load = [&](int stage, int kt) {
        const uint32_t base = sb + stage * STAGE_STRIDE;
        const int k0 = kt * 64;
        #pragma unroll
        for (int it = 0; it < 4; it++) {
            int idx = tid + it * 256;
            int row = idx >> 3, c = idx & 7;
            uint32_t so = SW128(row * 128 + c * 16);
            long ga = (long)row * sA + k0 + c * 8;
            long gb = (long)row * sB + k0 + c * 8;
            cpa16(base + so,           Ahi + ga);
            cpa16(base + OFF_ALO + so, Alo + ga);
            cpa16(base + OFF_BHI + so, Bhi + gb);
            cpa16(base + OFF_BLO + so, Blo + gb);
        }
    };

    float acc[64];
    #pragma unroll
    for (int i = 0; i < 64; i++) acc[i] = 0.f;

    stage_load(0, 0); CP_COMMIT();
    if (nkt > 1) stage_load(1, 1);
    CP_COMMIT();

    int st = 0;
    for (int kt = 0; kt < nkt; kt++) {
        if (kt + 1 < nkt) CP_WAIT1(); else CP_WAIT0();
        __syncthreads();
        if (kt + 2 < nkt) {
            int st2 = st + 2; if (st2 >= NSTAGE) st2 -= NSTAGE;
            stage_load(st2, kt + 2);
            CP_COMMIT();
        }
        const uint32_t base = sb + st * STAGE_STRIDE;
        #pragma unroll
        for (int ks = 0; ks < 4; ks++) {
            const int kb = ks * 32;
            uint32_t ah[16], al[16], bh[8], bl[8];
            load_afrags(base,           m0w, kb, lane, ah);
            load_bfrags(base + OFF_BHI, n0w, kb, lane, bh);
            load_bfrags(base + OFF_BLO, n0w, kb, lane, bl);
            load_afrags(base + OFF_ALO, m0w, kb, lane, al);
            #pragma unroll
            for (int i = 0; i < 4; i++)
                #pragma unroll
                for (int j = 0; j < 4; j++) {
                    float* c = acc + (i * 4 + j) * 4;
                    mma_bf16(c, ah + 4 * i, bh + 2 * j);
                    mma_bf16(c, ah + 4 * i, bl + 2 * j);
                    mma_bf16(c, al + 4 * i, bh + 2 * j);
                }
        }
        if (++st == NSTAGE) st = 0;
    }

    // ---- epilogue: MODE1 -> bf16 pair, MODE2 -> fp16 pair (+bias) ----
    #pragma unroll
    for (int i = 0; i < 4; i++) {
        #pragma unroll
        for (int j = 0; j < 4; j++) {
            const float* c = acc + (i * 4 + j) * 4;
            int r0 = m0w + 16 * i + (lane >> 2);
            int c0 = n0w + 8 * j + 2 * (lane & 3);
            float v0 = c[0], v1 = c[1], v2 = c[2], v3 = c[3];
            long o0 = outOfs + (long)r0 * ldc + coloff + c0;
            long o1 = outOfs + (long)(r0 + 8) * ldc + coloff + c0;
            if constexpr (MODE == 1) {
                __nv_bfloat16* outHi = (__nv_bfloat16*)outHiV;
                __nv_bfloat16* outLo = (__nv_bfloat16*)outLoV;
                __nv_bfloat16 h0, l0, h1, l1;
                split1(v0, h0, l0); split1(v1, h1, l1);
                *(uint32_t*)&outHi[o0] = pack2(h0, h1);
                *(uint32_t*)&outLo[o0] = pack2(l0, l1);
                split1(v2, h0, l0); split1(v3, h1, l1);
                *(uint32_t*)&outHi[o1] = pack2(h0, h1);
                *(uint32_t*)&outLo[o1] = pack2(l0, l1);
            } else {
                float b0 = __ldg(&bias[c0]), b1 = __ldg(&bias[c0 + 1]);
                v0 += b0; v1 += b1; v2 += b0; v3 += b1;
                __half* outHi = (__half*)outHiV;
                __half* outLo = (__half*)outLoV;
                __half h0, l0, h1, l1;
                split1h(v0, h0, l0); split1h(v1, h1, l1);
                *(uint32_t*)&outHi[o0] = pack2h(h0, h1);
                *(uint32_t*)&outLo[o0] = pack2h(l0, l1);
                split1h(v2, h0, l0); split1h(v3, h1, l1);
                *(uint32_t*)&outHi[o1] = pack2h(h0, h1);
                *(uint32_t*)&outLo[o1] = pack2h(l0, l1);
            }
        }
    }
}

// ---------------------------------------------------------------------------
// gemm_fc: fp16 asymmetric 2-term. C = mid[128,K] * fcw[128,K]^T (K=KSLICE)
// A = mid hi/lo fp16 pair, B = fcw single fp16. 2-stage pipeline (48KB/stage).
// grid = (SPLITS, BATCH/128, 2)
// ---------------------------------------------------------------------------
#define FC_OFF_ALO 16384
#define FC_OFF_B   32768
#define FC_STAGE   49152
#define FC_SMEM (2 * FC_STAGE + 1024)

__global__ void __launch_bounds__(256, 1)
gemm_fc(const __half* __restrict__ Ahi, const __half* __restrict__ Alo,
        const __half* __restrict__ B, float* __restrict__ outF)
{
    extern __shared__ char smraw[];
    char* sm = (char*)(((uintptr_t)smraw + 1023) & ~(uintptr_t)1023);
    const uint32_t sb = smem_u32(sm);

    const int tid  = threadIdx.x;
    const int lane = tid & 31;
    const int w    = tid >> 5;
    const int m0w  = (w >> 2) * 64;
    const int n0w  = (w & 3) * 32;

    const long split = blockIdx.x, mb = blockIdx.y, nh = blockIdx.z;
    Ahi += (mb * 128) * (long)KTOT + split * KSLICE;
    Alo += (mb * 128) * (long)KTOT + split * KSLICE;
    B   += (nh * 128) * (long)KTOT + split * KSLICE;
    outF += split * (long)SEC + (mb * 128) * (long)NFEAT + nh * 128;

    auto stage_load = [&](int stage, int kt) {
        const uint32_t base = sb + stage * FC_STAGE;
        const int k0 = kt * 64;
        #pragma unroll
        for (int it = 0; it < 4; it++) {
            int idx = tid + it * 256;
            int row = idx >> 3, c = idx & 7;
            uint32_t so = SW128(row * 128 + c * 16);
            long ga = (long)row * KTOT + k0 + c * 8;
            cpa16(base + so,            Ahi + ga);
            cpa16(base + FC_OFF_ALO + so, Alo + ga);
            cpa16(base + FC_OFF_B + so,   B + ga);
        }
    };

    float acc[64];
    #pragma unroll
    for (int i = 0; i < 64; i++) acc[i] = 0.f;

    const int nkt = KSLICE / 64;   // 32
    stage_load(0, 0); CP_COMMIT();
    stage_load(1, 1); CP_COMMIT();

    for (int kt = 0; kt < nkt; kt++) {
        const int st = kt & 1;
        if (kt + 1 < nkt) CP_WAIT1(); else CP_WAIT0();
        __syncthreads();

        const uint32_t base = sb + st * FC_STAGE;
        #pragma unroll
        for (int ks = 0; ks < 4; ks++) {
            const int kb = ks * 32;
            uint32_t ah[16], al[16], bh[8];
            load_afrags(base,             m0w, kb, lane, ah);
            load_afrags(base + FC_OFF_ALO, m0w, kb, lane, al);
            load_b32(base + FC_OFF_B, n0w, kb, lane, bh);
            #pragma unroll
            for (int i = 0; i < 4; i++)
                #pragma unroll
                for (int j = 0; j < 4; j++) {
                    float* c = acc + (i * 4 + j) * 4;
                    const uint32_t* bj = bh + 4 * (j >> 1) + 2 * (j & 1);
                    mma_f16(c, ah + 4 * i, bj);
                    mma_f16(c, al + 4 * i, bj);
                }
        }
        __syncthreads();
        if (kt + 2 < nkt) { stage_load(st, kt + 2); }
        CP_COMMIT();
    }

    #pragma unroll
    for (int i = 0; i < 4; i++) {
        #pragma unroll
        for (int j = 0; j < 4; j++) {
            const float* c = acc + (i * 4 + j) * 4;
            int r0 = m0w + 16 * i + (lane >> 2);
            int c0 = n0w + 8 * j + 2 * (lane & 3);
            *(float2*)&outF[(long)r0 * NFEAT + c0]       = make_float2(c[0], c[1]);
            *(float2*)&outF[(long)(r0 + 8) * NFEAT + c0] = make_float2(c[2], c[3]);
        }
    }
}

// ---------------------------------------------------------------------------
// prep kernels
// ---------------------------------------------------------------------------
__global__ void __launch_bounds__(256)
split_arr(const float* __restrict__ src, __nv_bfloat16* __restrict__ hi,
          __nv_bfloat16* __restrict__ lo, long n4)
{
    long i = (long)blockIdx.x * 256 + threadIdx.x;
    if (i >= n4) return;
    float4 v = ((const float4*)src)[i];
    __nv_bfloat16 h0, h1, h2, h3, l0, l1, l2, l3;
    split1(v.x, h0, l0); split1(v.y, h1, l1);
    split1(v.z, h2, l2); split1(v.w, h3, l3);
    ((uint2*)hi)[i] = make_uint2(pack2(h0, h1), pack2(h2, h3));
    ((uint2*)lo)[i] = make_uint2(pack2(l0, l1), pack2(l2, l3));
}

// fp32 -> single fp16 (for fc_w)
__global__ void __launch_bounds__(256)
conv_h(const float* __restrict__ src, __half* __restrict__ dst, long n4)
{
    long i = (long)blockIdx.x * 256 + threadIdx.x;
    if (i >= n4) return;
    float4 v = ((const float4*)src)[i];
    ((uint2*)dst)[i] = make_uint2(
        pack2h(__float2half_rn(v.x), __float2half_rn(v.y)),
        pack2h(__float2half_rn(v.z), __float2half_rn(v.w)));
}

__global__ void __launch_bounds__(256)
prep_w(const float* __restrict__ wsrc, __nv_bfloat16* __restrict__ hi,
       __nv_bfloat16* __restrict__ lo)
{
    int g = blockIdx.x, f = threadIdx.x;
    float v = wsrc[(long)f * NFEAT + g];
    __nv_bfloat16 h, l; split1(v, h, l);
    hi[(long)g * NFEAT + f] = h;
    lo[(long)g * NFEAT + f] = l;
}

// ---------------------------------------------------------------------------
// finalize: reduce split-K partials + fc_b, write 3 output sections
// ---------------------------------------------------------------------------
__global__ void __launch_bounds__(256)
finalize(const float* __restrict__ P, const float* __restrict__ fc_b,
         const float* __restrict__ x, float* __restrict__ out)
{
    const int idx = blockIdx.x * blockDim.x + threadIdx.x;
    if (idx >= SEC) return;
    const int b = idx >> 8;
    const int f = idx & 255;
    float v = fc_b[f];
    #pragma unroll
    for (int s = 0; s < SPLITS; s++)
        v += P[(long)s * SEC + idx];
    out[idx]           = v;
    out[2 * SEC + idx] = v;
    out[SEC + idx]     = x[(long)b * KTOT + f];   // x[b,0,f]
}

// ---------------------------------------------------------------------------
extern "C" void kernel_launch(void* const* d_in, const int* in_sizes, int n_in,
                              void* d_out, int out_size)
{
    const float* x     = (const float*)d_in[0];
    const float* adj   = (const float*)d_in[1];
    const float* gcn_w = (const float*)d_in[2];
    const float* gcn_b = (const float*)d_in[3];
    const float* fc_w  = (const float*)d_in[4];
    const float* fc_b  = (const float*)d_in[5];
    float* out = (float*)d_out;

    __nv_bfloat16 *gwT_hi, *gwT_lo, *x_hi, *x_lo, *adj_hi, *adj_lo;
    __nv_bfloat16 *supT_hi, *supT_lo;
    __half *fcw_h, *mid_hi, *mid_lo;
    float* partial;
    cudaGetSymbolAddress((void**)&gwT_hi,  g_gwT_hi);
    cudaGetSymbolAddress((void**)&gwT_lo,  g_gwT_lo);
    cudaGetSymbolAddress((void**)&x_hi,    g_x_hi);
    cudaGetSymbolAddress((void**)&x_lo,    g_x_lo);
    cudaGetSymbolAddress((void**)&adj_hi,  g_adj_hi);
    cudaGetSymbolAddress((void**)&adj_lo,  g_adj_lo);
    cudaGetSymbolAddress((void**)&fcw_h,   g_fcw_h);
    cudaGetSymbolAddress((void**)&supT_hi, g_supT_hi);
    cudaGetSymbolAddress((void**)&supT_lo, g_supT_lo);
    cudaGetSymbolAddress((void**)&mid_hi,  g_mid_hi);
    cudaGetSymbolAddress((void**)&mid_lo,  g_mid_lo);
    cudaGetSymbolAddress((void**)&partial, g_partial);

    cudaFuncSetAttribute(gemm_p<1>, cudaFuncAttributeMaxDynamicSharedMemorySize, SMEM_BYTES);
    cudaFuncSetAttribute(gemm_p<2>, cudaFuncAttributeMaxDynamicSharedMemorySize, SMEM_BYTES);
    cudaFuncSetAttribute(gemm_fc,   cudaFuncAttributeMaxDynamicSharedMemorySize, FC_SMEM);

    // 0) preps
    prep_w<<<NFEAT, NFEAT>>>(gcn_w, gwT_hi, gwT_lo);
    {
        long n4 = (long)BATCH * NODES * NFEAT / 4;        // x -> bf16 pair
        split_arr<<<(unsigned)((n4 + 255) / 256), 256>>>(x, x_hi, x_lo, n4);
    }
    {
        long n4 = (long)BATCH * NODES * NODES / 4;        // adj -> bf16 pair
        split_arr<<<(unsigned)((n4 + 255) / 256), 256>>>(adj, adj_hi, adj_lo, n4);
    }
    {
        long n4 = (long)NFEAT * KTOT / 4;                 // fc_w -> single fp16
        conv_h<<<(unsigned)((n4 + 255) / 256), 256>>>(fc_w, fcw_h, n4);
    }

    // 1) supT[b][g][node] = sum_f gwT[g][f] * x_b[node][f]   (3-term bf16)
    {
        dim3 grid(BATCH, 2);
        gemm_p<1><<<grid, 256, SMEM_BYTES>>>(
            gwT_hi, gwT_lo, NFEAT, x_hi, x_lo, NFEAT,
            nullptr, supT_hi, supT_lo, 4);
    }
    // 2) mid[b][node][g] = sum_k adj_b[node][k]*supT_b[g][k] + gcn_b[g]  (3-term bf16, fp16 out)
    {
        dim3 grid(BATCH, 2);
        gemm_p<2><<<grid, 256, SMEM_BYTES>>>(
            adj_hi, adj_lo, NODES, supT_hi, supT_lo, NODES,
            gcn_b, mid_hi, mid_lo, 2);
    }
    // 3) partial[s][m][n] = sum_{k in slice} mid[m][k]*fcw[n][k]  (2-term fp16 asym)
    {
        dim3 grid(SPLITS, BATCH / 128, 2);
        gemm_fc<<<grid, 256, FC_SMEM>>>(mid_hi, mid_lo, fcw_h, partial);
    }
    // 4) reduce + bias + output sections
    finalize<<<SEC / 256, 256>>>(partial, fc_b, x, out);
}

// round 8
// speedup vs baseline: 1.3456x; 1.1761x over previous
#include <cuda_runtime.h>
#include <cuda_bf16.h>
#include <cuda_fp16.h>
#include <cstdint>

#define BATCH 512
#define NODES 128
#define NFEAT 256
#define KTOT  32768          // NODES*NFEAT
#define SPLITS 16
#define KSLICE 2048          // KTOT/SPLITS
#define SEC   (BATCH*NFEAT)  // 131072

// ---------------------------------------------------------------------------
// Scratch (__device__ globals; allocation is forbidden)
// ---------------------------------------------------------------------------
__device__ __half g_gwT_hi[NFEAT * NFEAT];                   // [g][f] fp16 pair
__device__ __half g_gwT_lo[NFEAT * NFEAT];
__device__ __half g_x_h[(size_t)BATCH * NODES * NFEAT];      // [b][node][f] single
__device__ __half g_adj_h[(size_t)BATCH * NODES * NODES];    // [b][n][m] single
__device__ __half g_fcw_h[(size_t)NFEAT * KTOT];             // [o][k] single
__device__ __half g_supT_hi[(size_t)BATCH * NFEAT * NODES];  // [b][g][node] pair
__device__ __half g_supT_lo[(size_t)BATCH * NFEAT * NODES];
__device__ __half g_mid_hi[(size_t)BATCH * NODES * NFEAT];   // [b][node][g] pair
__device__ __half g_mid_lo[(size_t)BATCH * NODES * NFEAT];
__device__ float  g_partial[(size_t)SPLITS * BATCH * NFEAT];

// ---------------------------------------------------------------------------
#define SW128(o) ((o) ^ (((o) >> 3) & 0x70))

__device__ __forceinline__ uint32_t smem_u32(const void* p) {
    uint32_t a;
    asm("{ .reg .u64 t; cvta.to.shared.u64 t, %1; cvt.u32.u64 %0, t; }"
        : "=r"(a) : "l"(p));
    return a;
}
__device__ __forceinline__ void split1h(float v, __half& h, __half& l) {
    h = __float2half_rn(v);
    l = __float2half_rn(v - __half2float(h));
}
__device__ __forceinline__ uint32_t pack2h(__half a, __half b) {
    __half2 t = __halves2half2(a, b);
    return *reinterpret_cast<uint32_t*>(&t);
}

// ---------------------------------------------------------------------------
// cp.async (base PTX, sm_80+)
// ---------------------------------------------------------------------------
__device__ __forceinline__ void cpa16(uint32_t s, const void* g) {
    asm volatile("cp.async.cg.shared.global [%0], [%1], 16;" :: "r"(s), "l"(g));
}
#define CP_COMMIT()  asm volatile("cp.async.commit_group;" ::: "memory")
#define CP_WAIT1()   asm volatile("cp.async.wait_group 1;" ::: "memory")
#define CP_WAIT0()   asm volatile("cp.async.wait_group 0;" ::: "memory")

// ---------------------------------------------------------------------------
// warp-MMA primitives (base PTX)
// ---------------------------------------------------------------------------
__device__ __forceinline__ void ldsm_x4(uint32_t addr, uint32_t* r) {
    asm volatile("ldmatrix.sync.aligned.m8n8.x4.shared.b16 {%0,%1,%2,%3}, [%4];"
        : "=r"(r[0]), "=r"(r[1]), "=r"(r[2]), "=r"(r[3]) : "r"(addr));
}
__device__ __forceinline__ void mma_f16(float* c, const uint32_t* a, const uint32_t* b) {
    asm volatile(
        "mma.sync.aligned.m16n8k16.row.col.f32.f16.f16.f32 "
        "{%0,%1,%2,%3}, {%4,%5,%6,%7}, {%8,%9}, {%0,%1,%2,%3};"
        : "+f"(c[0]), "+f"(c[1]), "+f"(c[2]), "+f"(c[3])
        : "r"(a[0]), "r"(a[1]), "r"(a[2]), "r"(a[3]), "r"(b[0]), "r"(b[1]));
}
// A frags, m64: 4 x ldsm_x4
__device__ __forceinline__ void load_afrags(uint32_t tbase, int m0w, int kb,
                                            int lane, uint32_t* a) {
    const int kpart = ((lane >> 4) << 4);
    #pragma unroll
    for (int i = 0; i < 4; i++) {
        int row = m0w + 16 * i + (lane & 15);
        ldsm_x4(tbase + SW128(row * 128 + kb + kpart), a + 4 * i);
    }
}
// B frags, n32 (4 n8-tiles) in 2 ldsm_x4 (verified R6/R7):
// tile j fragment at b + 4*(j>>1) + 2*(j&1)
__device__ __forceinline__ void load_b32(uint32_t tbase, int n0, int kb,
                                         int lane, uint32_t* b) {
    const int kpart = (((lane >> 3) & 1) << 4);
    const int tofs  = ((lane >> 4) & 1) * 8;
    int row = n0 + tofs + (lane & 7);
    ldsm_x4(tbase + SW128(row * 128 + kb + kpart),        b);
    ldsm_x4(tbase + SW128((row + 16) * 128 + kb + kpart), b + 4);
}
#define BJ(b, j) ((b) + 4 * ((j) >> 1) + 2 * ((j) & 1))

// ---------------------------------------------------------------------------
// Unified asymmetric fp16 GEMM: C[128,128] = A[128,K] * B[128,K]^T
// All tiles 2-term: exactly ONE operand is an fp16 hi/lo pair, other single.
// CTA 128x128, warp 64x32, 256 threads.
//  MODE 1 (pair=A): A=gwT pair, B=x single     -> supT fp16 pair   (ldc=NODES)
//  MODE 2 (pair=B): A=adj single, B=supT pair  -> mid fp16 pair+b  (ldc=NFEAT)
//  MODE 3 (pair=A): A=mid pair, B=fcw single   -> partial fp32     (ldc=NFEAT)
// Stage: 3 x 16KB arrays = 48KB. NST=3 for modes 1/2, NST=2 for mode 3.
// ---------------------------------------------------------------------------
#define OFF1 16384
#define OFF2 32768
#define STG  49152
#define SMEM3 (3 * STG + 1024)
#define SMEM2 (2 * STG + 1024)

template <int MODE>
__global__ void __launch_bounds__(256, 1)
gemm_a(const __half* __restrict__ P0, const __half* __restrict__ P1,
       const __half* __restrict__ S0, long sP, long sS,
       const float* __restrict__ bias,
       float* __restrict__ outF, __half* __restrict__ outHi,
       __half* __restrict__ outLo, int nkt)
{
    // P0/P1 = the paired operand (hi/lo), S0 = the single operand.
    // MODE 1,3: pair is A-side. MODE 2: pair is B-side.
    constexpr int NST = (MODE == 3) ? 2 : 3;

    extern __shared__ char smraw[];
    char* sm = (char*)(((uintptr_t)smraw + 1023) & ~(uintptr_t)1023);
    const uint32_t sb = smem_u32(sm);

    const int tid  = threadIdx.x;
    const int lane = tid & 31;
    const int w    = tid >> 5;
    const int m0w  = (w >> 2) * 64;
    const int n0w  = (w & 3) * 32;

    int ldc = 0, coloff = 0;
    long outOfs = 0;
    if constexpr (MODE == 1) {
        long b = blockIdx.x, mh = blockIdx.y;
        P0 += mh * 128 * NFEAT;  P1 += mh * 128 * NFEAT;      // gwT rows
        S0 += b * (long)(NODES * NFEAT);                       // x_b
        outOfs = b * (long)(NFEAT * NODES) + mh * 128 * NODES;
        ldc = NODES;
    } else if constexpr (MODE == 2) {
        long b = blockIdx.x, nh = blockIdx.y;
        S0 += b * (long)(NODES * NODES);                       // adj_b
        P0 += b * (long)(NFEAT * NODES) + nh * 128 * NODES;    // supT rows
        P1 += b * (long)(NFEAT * NODES) + nh * 128 * NODES;
        outOfs = b * (long)(NODES * NFEAT);
        bias += nh * 128;
        ldc = NFEAT; coloff = (int)nh * 128;
    } else {
        long split = blockIdx.x, mb = blockIdx.y, nh = blockIdx.z;
        P0 += (mb * 128) * (long)KTOT + split * KSLICE;        // mid
        P1 += (mb * 128) * (long)KTOT + split * KSLICE;
        S0 += (nh * 128) * (long)KTOT + split * KSLICE;        // fcw
        outF += split * (long)SEC + (mb * 128) * (long)NFEAT + nh * 128;
        ldc = NFEAT;
    }

    // stage arrays: [0]=P0, [OFF1]=P1, [OFF2]=S0; each 128 rows x 128B
    auto stage_load = [&](int stage, int kt) {
        const uint32_t base = sb + stage * STG;
        const int k0 = kt * 64;
        #pragma unroll
        for (int it = 0; it < 4; it++) {
            int idx = tid + it * 256;
            int row = idx >> 3, c = idx & 7;
            uint32_t so = SW128(row * 128 + c * 16);
            long gp = (long)row * sP + k0 + c * 8;
            long gs = (long)row * sS + k0 + c * 8;
            cpa16(base + so,        P0 + gp);
            cpa16(base + OFF1 + so, P1 + gp);
            cpa16(base + OFF2 + so, S0 + gs);
        }
    };

    float acc[64];
    #pragma unroll
    for (int i = 0; i < 64; i++) acc[i] = 0.f;

    stage_load(0, 0); CP_COMMIT();
    if (nkt > 1) stage_load(1, 1);
    CP_COMMIT();

    int st = 0;
    for (int kt = 0; kt < nkt; kt++) {
        if (kt + 1 < nkt) CP_WAIT1(); else CP_WAIT0();
        __syncthreads();
        if constexpr (NST == 3) {
            // 3-stage: issue next-next load before compute (slot freed at kt-1)
            if (kt + 2 < nkt) {
                int st2 = st + 2; if (st2 >= NST) st2 -= NST;
                stage_load(st2, kt + 2);
                CP_COMMIT();
            }
        }
        const uint32_t base = sb + st * STG;
        #pragma unroll
        for (int ks = 0; ks < 4; ks++) {
            const int kb = ks * 32;
            if constexpr (MODE == 2) {
                // A single (adj), B pair (supT)
                uint32_t ah[16], bh[8], bl[8];
                load_afrags(base + OFF2, m0w, kb, lane, ah);
                load_b32(base,        n0w, kb, lane, bh);
                load_b32(base + OFF1, n0w, kb, lane, bl);
                #pragma unroll
                for (int i = 0; i < 4; i++)
                    #pragma unroll
                    for (int j = 0; j < 4; j++) {
                        float* c = acc + (i * 4 + j) * 4;
                        mma_f16(c, ah + 4 * i, BJ(bh, j));
                        mma_f16(c, ah + 4 * i, BJ(bl, j));
                    }
            } else {
                // A pair, B single
                uint32_t ah[16], al[16], b1[8];
                load_afrags(base,        m0w, kb, lane, ah);
                load_afrags(base + OFF1, m0w, kb, lane, al);
                load_b32(base + OFF2, n0w, kb, lane, b1);
                #pragma unroll
                for (int i = 0; i < 4; i++)
                    #pragma unroll
                    for (int j = 0; j < 4; j++) {
                        float* c = acc + (i * 4 + j) * 4;
                        mma_f16(c, ah + 4 * i, BJ(b1, j));
                        mma_f16(c, al + 4 * i, BJ(b1, j));
                    }
            }
        }
        if constexpr (NST == 2) {
            __syncthreads();
            if (kt + 2 < nkt) { stage_load(st, kt + 2); }
            CP_COMMIT();
        }
        if (++st == NST) st = 0;
    }

    // ---- epilogue ----
    #pragma unroll
    for (int i = 0; i < 4; i++) {
        #pragma unroll
        for (int j = 0; j < 4; j++) {
            const float* c = acc + (i * 4 + j) * 4;
            int r0 = m0w + 16 * i + (lane >> 2);
            int c0 = n0w + 8 * j + 2 * (lane & 3);
            if constexpr (MODE == 3) {
                *(float2*)&outF[(long)r0 * ldc + c0]       = make_float2(c[0], c[1]);
                *(float2*)&outF[(long)(r0 + 8) * ldc + c0] = make_float2(c[2], c[3]);
            } else {
                float v0 = c[0], v1 = c[1], v2 = c[2], v3 = c[3];
                if constexpr (MODE == 2) {
                    float b0 = __ldg(&bias[c0]), b1 = __ldg(&bias[c0 + 1]);
                    v0 += b0; v1 += b1; v2 += b0; v3 += b1;
                }
                long o0 = outOfs + (long)r0 * ldc + coloff + c0;
                long o1 = outOfs + (long)(r0 + 8) * ldc + coloff + c0;
                __half h0, l0, h1, l1;
                split1h(v0, h0, l0); split1h(v1, h1, l1);
                *(uint32_t*)&outHi[o0] = pack2h(h0, h1);
                *(uint32_t*)&outLo[o0] = pack2h(l0, l1);
                split1h(v2, h0, l0); split1h(v3, h1, l1);
                *(uint32_t*)&outHi[o1] = pack2h(h0, h1);
                *(uint32_t*)&outLo[o1] = pack2h(l0, l1);
            }
        }
    }
}

// ---------------------------------------------------------------------------
// prep kernels
// ---------------------------------------------------------------------------
// fp32 -> single fp16 (x, adj, fc_w)
__global__ void __launch_bounds__(256)
conv_h(const float* __restrict__ src, __half* __restrict__ dst, long n4)
{
    long i = (long)blockIdx.x * 256 + threadIdx.x;
    if (i >= n4) return;
    float4 v = ((const float4*)src)[i];
    ((uint2*)dst)[i] = make_uint2(
        pack2h(__float2half_rn(v.x), __float2half_rn(v.y)),
        pack2h(__float2half_rn(v.z), __float2half_rn(v.w)));
}

// gcn_w transpose + fp16 pair split
__global__ void __launch_bounds__(256)
prep_wh(const float* __restrict__ wsrc, __half* __restrict__ hi,
        __half* __restrict__ lo)
{
    int g = blockIdx.x, f = threadIdx.x;
    float v = wsrc[(long)f * NFEAT + g];
    __half h, l; split1h(v, h, l);
    hi[(long)g * NFEAT + f] = h;
    lo[(long)g * NFEAT + f] = l;
}

// ---------------------------------------------------------------------------
// finalize: reduce split-K partials + fc_b, write 3 output sections
// ---------------------------------------------------------------------------
__global__ void __launch_bounds__(256)
finalize(const float* __restrict__ P, const float* __restrict__ fc_b,
         const float* __restrict__ x, float* __restrict__ out)
{
    const int idx = blockIdx.x * blockDim.x + threadIdx.x;
    if (idx >= SEC) return;
    const int b = idx >> 8;
    const int f = idx & 255;
    float v = fc_b[f];
    #pragma unroll
    for (int s = 0; s < SPLITS; s++)
        v += P[(long)s * SEC + idx];
    out[idx]           = v;
    out[2 * SEC + idx] = v;
    out[SEC + idx]     = x[(long)b * KTOT + f];   // x[b,0,f]
}

// ---------------------------------------------------------------------------
extern "C" void kernel_launch(void* const* d_in, const int* in_sizes, int n_in,
                              void* d_out, int out_size)
{
    const float* x     = (const float*)d_in[0];
    const float* adj   = (const float*)d_in[1];
    const float* gcn_w = (const float*)d_in[2];
    const float* gcn_b = (const float*)d_in[3];
    const float* fc_w  = (const float*)d_in[4];
    const float* fc_b  = (const float*)d_in[5];
    float* out = (float*)d_out;

    __half *gwT_hi, *gwT_lo, *x_h, *adj_h, *fcw_h;
    __half *supT_hi, *supT_lo, *mid_hi, *mid_lo;
    float* partial;
    cudaGetSymbolAddress((void**)&gwT_hi,  g_gwT_hi);
    cudaGetSymbolAddress((void**)&gwT_lo,  g_gwT_lo);
    cudaGetSymbolAddress((void**)&x_h,     g_x_h);
    cudaGetSymbolAddress((void**)&adj_h,   g_adj_h);
    cudaGetSymbolAddress((void**)&fcw_h,   g_fcw_h);
    cudaGetSymbolAddress((void**)&supT_hi, g_supT_hi);
    cudaGetSymbolAddress((void**)&supT_lo, g_supT_lo);
    cudaGetSymbolAddress((void**)&mid_hi,  g_mid_hi);
    cudaGetSymbolAddress((void**)&mid_lo,  g_mid_lo);
    cudaGetSymbolAddress((void**)&partial, g_partial);

    cudaFuncSetAttribute(gemm_a<1>, cudaFuncAttributeMaxDynamicSharedMemorySize, SMEM3);
    cudaFuncSetAttribute(gemm_a<2>, cudaFuncAttributeMaxDynamicSharedMemorySize, SMEM3);
    cudaFuncSetAttribute(gemm_a<3>, cudaFuncAttributeMaxDynamicSharedMemorySize, SMEM2);

    // 0) preps
    prep_wh<<<NFEAT, NFEAT>>>(gcn_w, gwT_hi, gwT_lo);
    {
        long n4 = (long)BATCH * NODES * NFEAT / 4;
        conv_h<<<(unsigned)((n4 + 255) / 256), 256>>>(x, x_h, n4);
    }
    {
        long n4 = (long)BATCH * NODES * NODES / 4;
        conv_h<<<(unsigned)((n4 + 255) / 256), 256>>>(adj, adj_h, n4);
    }
    {
        long n4 = (long)NFEAT * KTOT / 4;
        conv_h<<<(unsigned)((n4 + 255) / 256), 256>>>(fc_w, fcw_h, n4);
    }

    // 1) supT[b][g][node] = sum_f gwT[g][f] * x_b[node][f]
    {
        dim3 grid(BATCH, 2);
        gemm_a<1><<<grid, 256, SMEM3>>>(
            gwT_hi, gwT_lo, x_h, NFEAT, NFEAT,
            nullptr, nullptr, supT_hi, supT_lo, 4);
    }
    // 2) mid[b][node][g] = sum_k adj_b[node][k]*supT_b[g][k] + gcn_b[g]
    {
        dim3 grid(BATCH, 2);
        gemm_a<2><<<grid, 256, SMEM3>>>(
            supT_hi, supT_lo, adj_h, NODES, NODES,
            gcn_b, nullptr, mid_hi, mid_lo, 2);
    }
    // 3) partial[s][m][n] = sum_{k in slice} mid[m][k]*fcw[n][k]
    {
        dim3 grid(SPLITS, BATCH / 128, 2);
        gemm_a<3><<<grid, 256, SMEM2>>>(
            mid_hi, mid_lo, fcw_h, KTOT, KTOT,
            nullptr, partial, nullptr, nullptr, KSLICE / 64);
    }
    // 4) reduce + bias + output sections
    finalize<<<SEC / 256, 256>>>(partial, fc_b, x, out);
}

// round 9
// speedup vs baseline: 1.4417x; 1.0714x over previous
#include <cuda_runtime.h>
#include <cuda_bf16.h>
#include <cuda_fp16.h>
#include <cstdint>

#define BATCH 512
#define NODES 128
#define NFEAT 256
#define KTOT  32768          // NODES*NFEAT
#define SPLITS 32
#define KSLICE 1024          // KTOT/SPLITS
#define SEC   (BATCH*NFEAT)  // 131072

// ---------------------------------------------------------------------------
// Scratch (__device__ globals; allocation is forbidden)
// ---------------------------------------------------------------------------
__device__ __half g_gwT_hi[NFEAT * NFEAT];                   // [g][f] fp16 pair
__device__ __half g_gwT_lo[NFEAT * NFEAT];
__device__ __half g_x_h[(size_t)BATCH * NODES * NFEAT];      // [b][node][f] single
__device__ __half g_adj_h[(size_t)BATCH * NODES * NODES];    // [b][n][m] single
__device__ __half g_fcw_h[(size_t)NFEAT * KTOT];             // [o][k] single
__device__ __half g_supT_hi[(size_t)BATCH * NFEAT * NODES];  // [b][g][node] pair
__device__ __half g_supT_lo[(size_t)BATCH * NFEAT * NODES];
__device__ __half g_mid_hi[(size_t)BATCH * NODES * NFEAT];   // [b][node][g] pair
__device__ __half g_mid_lo[(size_t)BATCH * NODES * NFEAT];
__device__ float  g_partial[(size_t)SPLITS * BATCH * NFEAT];

// ---------------------------------------------------------------------------
#define SW128(o) ((o) ^ (((o) >> 3) & 0x70))

__device__ __forceinline__ uint32_t smem_u32(const void* p) {
    uint32_t a;
    asm("{ .reg .u64 t; cvta.to.shared.u64 t, %1; cvt.u32.u64 %0, t; }"
        : "=r"(a) : "l"(p));
    return a;
}
__device__ __forceinline__ void split1h(float v, __half& h, __half& l) {
    h = __float2half_rn(v);
    l = __float2half_rn(v - __half2float(h));
}
__device__ __forceinline__ uint32_t pack2h(__half a, __half b) {
    __half2 t = __halves2half2(a, b);
    return *reinterpret_cast<uint32_t*>(&t);
}

// ---------------------------------------------------------------------------
// cp.async (base PTX, sm_80+)
// ---------------------------------------------------------------------------
__device__ __forceinline__ void cpa16(uint32_t s, const void* g) {
    asm volatile("cp.async.cg.shared.global [%0], [%1], 16;" :: "r"(s), "l"(g));
}
#define CP_COMMIT()  asm volatile("cp.async.commit_group;" ::: "memory")
#define CP_WAIT1()   asm volatile("cp.async.wait_group 1;" ::: "memory")
#define CP_WAIT0()   asm volatile("cp.async.wait_group 0;" ::: "memory")

// ---------------------------------------------------------------------------
// warp-MMA primitives (base PTX)
// ---------------------------------------------------------------------------
__device__ __forceinline__ void ldsm_x4(uint32_t addr, uint32_t* r) {
    asm volatile("ldmatrix.sync.aligned.m8n8.x4.shared.b16 {%0,%1,%2,%3}, [%4];"
        : "=r"(r[0]), "=r"(r[1]), "=r"(r[2]), "=r"(r[3]) : "r"(addr));
}
__device__ __forceinline__ void mma_f16(float* c, const uint32_t* a, const uint32_t* b) {
    asm volatile(
        "mma.sync.aligned.m16n8k16.row.col.f32.f16.f16.f32 "
        "{%0,%1,%2,%3}, {%4,%5,%6,%7}, {%8,%9}, {%0,%1,%2,%3};"
        : "+f"(c[0]), "+f"(c[1]), "+f"(c[2]), "+f"(c[3])
        : "r"(a[0]), "r"(a[1]), "r"(a[2]), "r"(a[3]), "r"(b[0]), "r"(b[1]));
}
// A frags, m64: 4 x ldsm_x4
__device__ __forceinline__ void load_afrags(uint32_t tbase, int m0w, int kb,
                                            int lane, uint32_t* a) {
    const int kpart = ((lane >> 4) << 4);
    #pragma unroll
    for (int i = 0; i < 4; i++) {
        int row = m0w + 16 * i + (lane & 15);
        ldsm_x4(tbase + SW128(row * 128 + kb + kpart), a + 4 * i);
    }
}
// B frags, n32 (4 n8-tiles) in 2 ldsm_x4; tile j at b + 4*(j>>1) + 2*(j&1)
__device__ __forceinline__ void load_b32(uint32_t tbase, int n0, int kb,
                                         int lane, uint32_t* b) {
    const int kpart = (((lane >> 3) & 1) << 4);
    const int tofs  = ((lane >> 4) & 1) * 8;
    int row = n0 + tofs + (lane & 7);
    ldsm_x4(tbase + SW128(row * 128 + kb + kpart),        b);
    ldsm_x4(tbase + SW128((row + 16) * 128 + kb + kpart), b + 4);
}
#define BJ(b, j) ((b) + 4 * ((j) >> 1) + 2 * ((j) & 1))

// ---------------------------------------------------------------------------
// Unified asymmetric fp16 GEMM: C[128,128] = A[128,K] * B[128,K]^T
// Exactly ONE operand is an fp16 hi/lo pair, other single. 2 MMAs per k16.
// CTA 128x128, warp 64x32, 256 threads, 2-stage pipeline, OCCUPANCY 2.
//  MODE 1 (pair=A): A=gwT pair, B=x single     -> supT fp16 pair   (ldc=NODES)
//  MODE 2 (pair=B): A=adj single, B=supT pair  -> mid fp16 pair+b  (ldc=NFEAT)
//  MODE 3 (pair=A): A=mid pair, B=fcw single   -> partial fp32     (ldc=NFEAT)
// ---------------------------------------------------------------------------
#define OFF1 16384
#define OFF2 32768
#define STG  49152
#define SMEM2 (2 * STG + 1024)   // 99328 B; 2 CTAs = 198656 <= 228KB

template <int MODE>
__global__ void __launch_bounds__(256, 2)
gemm_a(const __half* __restrict__ P0, const __half* __restrict__ P1,
       const __half* __restrict__ S0, long sP, long sS,
       const float* __restrict__ bias,
       float* __restrict__ outF, __half* __restrict__ outHi,
       __half* __restrict__ outLo, int nkt)
{
    extern __shared__ char smraw[];
    char* sm = (char*)(((uintptr_t)smraw + 1023) & ~(uintptr_t)1023);
    const uint32_t sb = smem_u32(sm);

    const int tid  = threadIdx.x;
    const int lane = tid & 31;
    const int w    = tid >> 5;
    const int m0w  = (w >> 2) * 64;
    const int n0w  = (w & 3) * 32;

    int ldc = 0, coloff = 0;
    long outOfs = 0;
    if constexpr (MODE == 1) {
        long b = blockIdx.x, mh = blockIdx.y;
        P0 += mh * 128 * NFEAT;  P1 += mh * 128 * NFEAT;      // gwT rows
        S0 += b * (long)(NODES * NFEAT);                       // x_b
        outOfs = b * (long)(NFEAT * NODES) + mh * 128 * NODES;
        ldc = NODES;
    } else if constexpr (MODE == 2) {
        long b = blockIdx.x, nh = blockIdx.y;
        S0 += b * (long)(NODES * NODES);                       // adj_b
        P0 += b * (long)(NFEAT * NODES) + nh * 128 * NODES;    // supT rows
        P1 += b * (long)(NFEAT * NODES) + nh * 128 * NODES;
        outOfs = b * (long)(NODES * NFEAT);
        bias += nh * 128;
        ldc = NFEAT; coloff = (int)nh * 128;
    } else {
        long split = blockIdx.x, mb = blockIdx.y, nh = blockIdx.z;
        P0 += (mb * 128) * (long)KTOT + split * KSLICE;        // mid
        P1 += (mb * 128) * (long)KTOT + split * KSLICE;
        S0 += (nh * 128) * (long)KTOT + split * KSLICE;        // fcw
        outF += split * (long)SEC + (mb * 128) * (long)NFEAT + nh * 128;
        ldc = NFEAT;
    }

    // stage arrays: [0]=P0, [OFF1]=P1, [OFF2]=S0; each 128 rows x 128B
    auto stage_load = [&](int stage, int kt) {
        const uint32_t base = sb + stage * STG;
        const int k0 = kt * 64;
        #pragma unroll
        for (int it = 0; it < 4; it++) {
            int idx = tid + it * 256;
            int row = idx >> 3, c = idx & 7;
            uint32_t so = SW128(row * 128 + c * 16);
            long gp = (long)row * sP + k0 + c * 8;
            long gs = (long)row * sS + k0 + c * 8;
            cpa16(base + so,        P0 + gp);
            cpa16(base + OFF1 + so, P1 + gp);
            cpa16(base + OFF2 + so, S0 + gs);
        }
    };

    float acc[64];
    #pragma unroll
    for (int i = 0; i < 64; i++) acc[i] = 0.f;

    stage_load(0, 0); CP_COMMIT();
    if (nkt > 1) stage_load(1, 1);
    CP_COMMIT();

    for (int kt = 0; kt < nkt; kt++) {
        const int st = kt & 1;
        if (kt + 1 < nkt) CP_WAIT1(); else CP_WAIT0();
        __syncthreads();

        const uint32_t base = sb + st * STG;
        #pragma unroll
        for (int ks = 0; ks < 4; ks++) {
            const int kb = ks * 32;
            if constexpr (MODE == 2) {
                // A single (adj), B pair (supT)
                uint32_t ah[16], bh[8], bl[8];
                load_afrags(base + OFF2, m0w, kb, lane, ah);
                load_b32(base,        n0w, kb, lane, bh);
                load_b32(base + OFF1, n0w, kb, lane, bl);
                #pragma unroll
                for (int i = 0; i < 4; i++)
                    #pragma unroll
                    for (int j = 0; j < 4; j++) {
                        float* c = acc + (i * 4 + j) * 4;
                        mma_f16(c, ah + 4 * i, BJ(bh, j));
                        mma_f16(c, ah + 4 * i, BJ(bl, j));
                    }
            } else {
                // A pair, B single
                uint32_t ah[16], al[16], b1[8];
                load_afrags(base,        m0w, kb, lane, ah);
                load_afrags(base + OFF1, m0w, kb, lane, al);
                load_b32(base + OFF2, n0w, kb, lane, b1);
                #pragma unroll
                for (int i = 0; i < 4; i++)
                    #pragma unroll
                    for (int j = 0; j < 4; j++) {
                        float* c = acc + (i * 4 + j) * 4;
                        mma_f16(c, ah + 4 * i, BJ(b1, j));
                        mma_f16(c, al + 4 * i, BJ(b1, j));
                    }
            }
        }
        __syncthreads();
        if (kt + 2 < nkt) { stage_load(st, kt + 2); }
        CP_COMMIT();
    }

    // ---- epilogue ----
    #pragma unroll
    for (int i = 0; i < 4; i++) {
        #pragma unroll
        for (int j = 0; j < 4; j++) {
            const float* c = acc + (i * 4 + j) * 4;
            int r0 = m0w + 16 * i + (lane >> 2);
            int c0 = n0w + 8 * j + 2 * (lane & 3);
            if constexpr (MODE == 3) {
                *(float2*)&outF[(long)r0 * ldc + c0]       = make_float2(c[0], c[1]);
                *(float2*)&outF[(long)(r0 + 8) * ldc + c0] = make_float2(c[2], c[3]);
            } else {
                float v0 = c[0], v1 = c[1], v2 = c[2], v3 = c[3];
                if constexpr (MODE == 2) {
                    float b0 = __ldg(&bias[c0]), b1 = __ldg(&bias[c0 + 1]);
                    v0 += b0; v1 += b1; v2 += b0; v3 += b1;
                }
                long o0 = outOfs + (long)r0 * ldc + coloff + c0;
                long o1 = outOfs + (long)(r0 + 8) * ldc + coloff + c0;
                __half h0, l0, h1, l1;
                split1h(v0, h0, l0); split1h(v1, h1, l1);
                *(uint32_t*)&outHi[o0] = pack2h(h0, h1);
                *(uint32_t*)&outLo[o0] = pack2h(l0, l1);
                split1h(v2, h0, l0); split1h(v3, h1, l1);
                *(uint32_t*)&outHi[o1] = pack2h(h0, h1);
                *(uint32_t*)&outLo[o1] = pack2h(l0, l1);
            }
        }
    }
}

// ---------------------------------------------------------------------------
// prep kernels
// ---------------------------------------------------------------------------
__global__ void __launch_bounds__(256)
conv_h(const float* __restrict__ src, __half* __restrict__ dst, long n4)
{
    long i = (long)blockIdx.x * 256 + threadIdx.x;
    if (i >= n4) return;
    float4 v = ((const float4*)src)[i];
    ((uint2*)dst)[i] = make_uint2(
        pack2h(__float2half_rn(v.x), __float2half_rn(v.y)),
        pack2h(__float2half_rn(v.z), __float2half_rn(v.w)));
}

__global__ void __launch_bounds__(256)
prep_wh(const float* __restrict__ wsrc, __half* __restrict__ hi,
        __half* __restrict__ lo)
{
    int g = blockIdx.x, f = threadIdx.x;
    float v = wsrc[(long)f * NFEAT + g];
    __half h, l; split1h(v, h, l);
    hi[(long)g * NFEAT + f] = h;
    lo[(long)g * NFEAT + f] = l;
}

// ---------------------------------------------------------------------------
// finalize: reduce split-K partials + fc_b, write 3 output sections
// ---------------------------------------------------------------------------
__global__ void __launch_bounds__(256)
finalize(const float* __restrict__ P, const float* __restrict__ fc_b,
         const float* __restrict__ x, float* __restrict__ out)
{
    const int idx = blockIdx.x * blockDim.x + threadIdx.x;
    if (idx >= SEC) return;
    const int b = idx >> 8;
    const int f = idx & 255;
    float v = fc_b[f];
    #pragma unroll
    for (int s = 0; s < SPLITS; s++)
        v += P[(long)s * SEC + idx];
    out[idx]           = v;
    out[2 * SEC + idx] = v;
    out[SEC + idx]     = x[(long)b * KTOT + f];   // x[b,0,f]
}

// ---------------------------------------------------------------------------
extern "C" void kernel_launch(void* const* d_in, const int* in_sizes, int n_in,
                              void* d_out, int out_size)
{
    const float* x     = (const float*)d_in[0];
    const float* adj   = (const float*)d_in[1];
    const float* gcn_w = (const float*)d_in[2];
    const float* gcn_b = (const float*)d_in[3];
    const float* fc_w  = (const float*)d_in[4];
    const float* fc_b  = (const float*)d_in[5];
    float* out = (float*)d_out;

    __half *gwT_hi, *gwT_lo, *x_h, *adj_h, *fcw_h;
    __half *supT_hi, *supT_lo, *mid_hi, *mid_lo;
    float* partial;
    cudaGetSymbolAddress((void**)&gwT_hi,  g_gwT_hi);
    cudaGetSymbolAddress((void**)&gwT_lo,  g_gwT_lo);
    cudaGetSymbolAddress((void**)&x_h,     g_x_h);
    cudaGetSymbolAddress((void**)&adj_h,   g_adj_h);
    cudaGetSymbolAddress((void**)&fcw_h,   g_fcw_h);
    cudaGetSymbolAddress((void**)&supT_hi, g_supT_hi);
    cudaGetSymbolAddress((void**)&supT_lo, g_supT_lo);
    cudaGetSymbolAddress((void**)&mid_hi,  g_mid_hi);
    cudaGetSymbolAddress((void**)&mid_lo,  g_mid_lo);
    cudaGetSymbolAddress((void**)&partial, g_partial);

    cudaFuncSetAttribute(gemm_a<1>, cudaFuncAttributeMaxDynamicSharedMemorySize, SMEM2);
    cudaFuncSetAttribute(gemm_a<2>, cudaFuncAttributeMaxDynamicSharedMemorySize, SMEM2);
    cudaFuncSetAttribute(gemm_a<3>, cudaFuncAttributeMaxDynamicSharedMemorySize, SMEM2);

    // 0) preps
    prep_wh<<<NFEAT, NFEAT>>>(gcn_w, gwT_hi, gwT_lo);
    {
        long n4 = (long)BATCH * NODES * NFEAT / 4;
        conv_h<<<(unsigned)((n4 + 255) / 256), 256>>>(x, x_h, n4);
    }
    {
        long n4 = (long)BATCH * NODES * NODES / 4;
        conv_h<<<(unsigned)((n4 + 255) / 256), 256>>>(adj, adj_h, n4);
    }
    {
        long n4 = (long)NFEAT * KTOT / 4;
        conv_h<<<(unsigned)((n4 + 255) / 256), 256>>>(fc_w, fcw_h, n4);
    }

    // 1) supT[b][g][node] = sum_f gwT[g][f] * x_b[node][f]
    {
        dim3 grid(BATCH, 2);
        gemm_a<1><<<grid, 256, SMEM2>>>(
            gwT_hi, gwT_lo, x_h, NFEAT, NFEAT,
            nullptr, nullptr, supT_hi, supT_lo, 4);
    }
    // 2) mid[b][node][g] = sum_k adj_b[node][k]*supT_b[g][k] + gcn_b[g]
    {
        dim3 grid(BATCH, 2);
        gemm_a<2><<<grid, 256, SMEM2>>>(
            supT_hi, supT_lo, adj_h, NODES, NODES,
            gcn_b, nullptr, mid_hi, mid_lo, 2);
    }
    // 3) partial[s][m][n] = sum_{k in slice} mid[m][k]*fcw[n][k]
    {
        dim3 grid(SPLITS, BATCH / 128, 2);
        gemm_a<3><<<grid, 256, SMEM2>>>(
            mid_hi, mid_lo, fcw_h, KTOT, KTOT,
            nullptr, partial, nullptr, nullptr, KSLICE / 64);
    }
    // 4) reduce + bias + output sections
    finalize<<<SEC / 256, 256>>>(partial, fc_b, x, out);
}

// round 10
// speedup vs baseline: 2.1467x; 1.4890x over previous
#include <cuda_runtime.h>
#include <cuda_fp16.h>
#include <cstdint>

#define BATCH 512
#define NODES 128
#define NFEAT 256
#define KTOT  32768          // NODES*NFEAT
#define SPLITS 32
#define KSLICE 1024          // KTOT/SPLITS
#define SEC   (BATCH*NFEAT)  // 131072

// ---------------------------------------------------------------------------
// Scratch (__device__ globals; allocation is forbidden)
// ---------------------------------------------------------------------------
__device__ __half g_gwT_h[NFEAT * NFEAT];                    // [g][f]
__device__ __half g_x_h[(size_t)BATCH * NODES * NFEAT];      // [b][node][f]
__device__ __half g_adj_h[(size_t)BATCH * NODES * NODES];    // [b][n][m]
__device__ __half g_fcw_h[(size_t)NFEAT * KTOT];             // [o][k]
__device__ __half g_supT_h[(size_t)BATCH * NFEAT * NODES];   // [b][g][node]
__device__ __half g_mid_h[(size_t)BATCH * NODES * NFEAT];    // [b][node][g]
__device__ float  g_partial[(size_t)SPLITS * BATCH * NFEAT];

// ---------------------------------------------------------------------------
#define SW128(o) ((o) ^ (((o) >> 3) & 0x70))

__device__ __forceinline__ uint32_t smem_u32(const void* p) {
    uint32_t a;
    asm("{ .reg .u64 t; cvta.to.shared.u64 t, %1; cvt.u32.u64 %0, t; }"
        : "=r"(a) : "l"(p));
    return a;
}
__device__ __forceinline__ uint32_t pack2h(__half a, __half b) {
    __half2 t = __halves2half2(a, b);
    return *reinterpret_cast<uint32_t*>(&t);
}

// ---------------------------------------------------------------------------
// cp.async (base PTX, sm_80+)
// ---------------------------------------------------------------------------
__device__ __forceinline__ void cpa16(uint32_t s, const void* g) {
    asm volatile("cp.async.cg.shared.global [%0], [%1], 16;" :: "r"(s), "l"(g));
}
#define CP_COMMIT()  asm volatile("cp.async.commit_group;" ::: "memory")
#define CP_WAIT1()   asm volatile("cp.async.wait_group 1;" ::: "memory")
#define CP_WAIT0()   asm volatile("cp.async.wait_group 0;" ::: "memory")

// ---------------------------------------------------------------------------
// warp-MMA primitives (base PTX)
// ---------------------------------------------------------------------------
__device__ __forceinline__ void ldsm_x4(uint32_t addr, uint32_t* r) {
    asm volatile("ldmatrix.sync.aligned.m8n8.x4.shared.b16 {%0,%1,%2,%3}, [%4];"
        : "=r"(r[0]), "=r"(r[1]), "=r"(r[2]), "=r"(r[3]) : "r"(addr));
}
__device__ __forceinline__ void mma_f16(float* c, const uint32_t* a, const uint32_t* b) {
    asm volatile(
        "mma.sync.aligned.m16n8k16.row.col.f32.f16.f16.f32 "
        "{%0,%1,%2,%3}, {%4,%5,%6,%7}, {%8,%9}, {%0,%1,%2,%3};"
        : "+f"(c[0]), "+f"(c[1]), "+f"(c[2]), "+f"(c[3])
        : "r"(a[0]), "r"(a[1]), "r"(a[2]), "r"(a[3]), "r"(b[0]), "r"(b[1]));
}
// A frags, m64: 4 x ldsm_x4
__device__ __forceinline__ void load_afrags(uint32_t tbase, int m0w, int kb,
                                            int lane, uint32_t* a) {
    const int kpart = ((lane >> 4) << 4);
    #pragma unroll
    for (int i = 0; i < 4; i++) {
        int row = m0w + 16 * i + (lane & 15);
        ldsm_x4(tbase + SW128(row * 128 + kb + kpart), a + 4 * i);
    }
}
// B frags, n32 (4 n8-tiles) in 2 ldsm_x4; tile j at b + 4*(j>>1) + 2*(j&1)
__device__ __forceinline__ void load_b32(uint32_t tbase, int n0, int kb,
                                         int lane, uint32_t* b) {
    const int kpart = (((lane >> 3) & 1) << 4);
    const int tofs  = ((lane >> 4) & 1) * 8;
    int row = n0 + tofs + (lane & 7);
    ldsm_x4(tbase + SW128(row * 128 + kb + kpart),        b);
    ldsm_x4(tbase + SW128((row + 16) * 128 + kb + kpart), b + 4);
}
#define BJ(b, j) ((b) + 4 * ((j) >> 1) + 2 * ((j) & 1))

// ---------------------------------------------------------------------------
// Single-fp16 GEMM: C[128,128] = A[128,K] * B[128,K]^T, 1 MMA per k16.
// CTA 128x128, warp 64x32, 256 threads, 2-stage pipeline, occupancy 2.
//  MODE 1: A=gwT, B=x_b     -> supT fp16          (ldc=NODES)
//  MODE 2: A=adj_b, B=supT  -> mid fp16 + bias    (ldc=NFEAT)
//  MODE 3: A=mid, B=fcw     -> partial fp32       (ldc=NFEAT)
// Stage: A 16KB | B 16KB = 32KB.
// ---------------------------------------------------------------------------
#define OFF_B 16384
#define STG   32768
#define SMEM2 (2 * STG + 1024)   // 66560 B; 2 CTAs/SM = 133KB

template <int MODE>
__global__ void __launch_bounds__(256, 2)
gemm_s(const __half* __restrict__ A, const __half* __restrict__ B,
       long sA, long sB,
       const float* __restrict__ bias,
       float* __restrict__ outF, __half* __restrict__ outH, int nkt)
{
    extern __shared__ char smraw[];
    char* sm = (char*)(((uintptr_t)smraw + 1023) & ~(uintptr_t)1023);
    const uint32_t sb = smem_u32(sm);

    const int tid  = threadIdx.x;
    const int lane = tid & 31;
    const int w    = tid >> 5;
    const int m0w  = (w >> 2) * 64;
    const int n0w  = (w & 3) * 32;

    int ldc = 0, coloff = 0;
    long outOfs = 0;
    if constexpr (MODE == 1) {
        long b = blockIdx.x, mh = blockIdx.y;
        A += mh * 128 * NFEAT;                    // gwT rows
        B += b * (long)(NODES * NFEAT);           // x_b
        outOfs = b * (long)(NFEAT * NODES) + mh * 128 * NODES;
        ldc = NODES;
    } else if constexpr (MODE == 2) {
        long b = blockIdx.x, nh = blockIdx.y;
        A += b * (long)(NODES * NODES);           // adj_b
        B += b * (long)(NFEAT * NODES) + nh * 128 * NODES;   // supT rows
        outOfs = b * (long)(NODES * NFEAT);
        bias += nh * 128;
        ldc = NFEAT; coloff = (int)nh * 128;
    } else {
        long split = blockIdx.x, mb = blockIdx.y, nh = blockIdx.z;
        A += (mb * 128) * (long)KTOT + split * KSLICE;       // mid
        B += (nh * 128) * (long)KTOT + split * KSLICE;       // fcw
        outF += split * (long)SEC + (mb * 128) * (long)NFEAT + nh * 128;
        ldc = NFEAT;
    }

    // stage arrays: [0]=A, [OFF_B]=B; each 128 rows x 128B
    auto stage_load = [&](int stage, int kt) {
        const uint32_t base = sb + stage * STG;
        const int k0 = kt * 64;
        #pragma unroll
        for (int it = 0; it < 4; it++) {
            int idx = tid + it * 256;
            int row = idx >> 3, c = idx & 7;
            uint32_t so = SW128(row * 128 + c * 16);
            cpa16(base + so,         A + (long)row * sA + k0 + c * 8);
            cpa16(base + OFF_B + so, B + (long)row * sB + k0 + c * 8);
        }
    };

    float acc[64];
    #pragma unroll
    for (int i = 0; i < 64; i++) acc[i] = 0.f;

    stage_load(0, 0); CP_COMMIT();
    if (nkt > 1) stage_load(1, 1);
    CP_COMMIT();

    for (int kt = 0; kt < nkt; kt++) {
        const int st = kt & 1;
        if (kt + 1 < nkt) CP_WAIT1(); else CP_WAIT0();
        __syncthreads();

        const uint32_t base = sb + st * STG;
        #pragma unroll
        for (int ks = 0; ks < 4; ks++) {
            const int kb = ks * 32;
            uint32_t ah[16], b1[8];
            load_afrags(base,         m0w, kb, lane, ah);
            load_b32(base + OFF_B, n0w, kb, lane, b1);
            #pragma unroll
            for (int i = 0; i < 4; i++)
                #pragma unroll
                for (int j = 0; j < 4; j++)
                    mma_f16(acc + (i * 4 + j) * 4, ah + 4 * i, BJ(b1, j));
        }
        __syncthreads();
        if (kt + 2 < nkt) { stage_load(st, kt + 2); }
        CP_COMMIT();
    }

    // ---- epilogue ----
    #pragma unroll
    for (int i = 0; i < 4; i++) {
        #pragma unroll
        for (int j = 0; j < 4; j++) {
            const float* c = acc + (i * 4 + j) * 4;
            int r0 = m0w + 16 * i + (lane >> 2);
            int c0 = n0w + 8 * j + 2 * (lane & 3);
            if constexpr (MODE == 3) {
                *(float2*)&outF[(long)r0 * ldc + c0]       = make_float2(c[0], c[1]);
                *(float2*)&outF[(long)(r0 + 8) * ldc + c0] = make_float2(c[2], c[3]);
            } else {
                float v0 = c[0], v1 = c[1], v2 = c[2], v3 = c[3];
                if constexpr (MODE == 2) {
                    float b0 = __ldg(&bias[c0]), b1 = __ldg(&bias[c0 + 1]);
                    v0 += b0; v1 += b1; v2 += b0; v3 += b1;
                }
                long o0 = outOfs + (long)r0 * ldc + coloff + c0;
                long o1 = outOfs + (long)(r0 + 8) * ldc + coloff + c0;
                *(uint32_t*)&outH[o0] = pack2h(__float2half_rn(v0), __float2half_rn(v1));
                *(uint32_t*)&outH[o1] = pack2h(__float2half_rn(v2), __float2half_rn(v3));
            }
        }
    }
}

// ---------------------------------------------------------------------------
// prep kernels
// ---------------------------------------------------------------------------
__global__ void __launch_bounds__(256)
conv_h(const float* __restrict__ src, __half* __restrict__ dst, long n4)
{
    long i = (long)blockIdx.x * 256 + threadIdx.x;
    if (i >= n4) return;
    float4 v = ((const float4*)src)[i];
    ((uint2*)dst)[i] = make_uint2(
        pack2h(__float2half_rn(v.x), __float2half_rn(v.y)),
        pack2h(__float2half_rn(v.z), __float2half_rn(v.w)));
}

// gcn_w transpose -> single fp16
__global__ void __launch_bounds__(256)
prep_wh(const float* __restrict__ wsrc, __half* __restrict__ dst)
{
    int g = blockIdx.x, f = threadIdx.x;
    dst[(long)g * NFEAT + f] = __float2half_rn(wsrc[(long)f * NFEAT + g]);
}

// ---------------------------------------------------------------------------
// finalize: reduce split-K partials + fc_b, write 3 output sections
// ---------------------------------------------------------------------------
__global__ void __launch_bounds__(256)
finalize(const float* __restrict__ P, const float* __restrict__ fc_b,
         const float* __restrict__ x, float* __restrict__ out)
{
    const int idx = blockIdx.x * blockDim.x + threadIdx.x;
    if (idx >= SEC) return;
    const int b = idx >> 8;
    const int f = idx & 255;
    float v = fc_b[f];
    #pragma unroll
    for (int s = 0; s < SPLITS; s++)
        v += P[(long)s * SEC + idx];
    out[idx]           = v;
    out[2 * SEC + idx] = v;
    out[SEC + idx]     = x[(long)b * KTOT + f];   // x[b,0,f]
}

// ---------------------------------------------------------------------------
extern "C" void kernel_launch(void* const* d_in, const int* in_sizes, int n_in,
                              void* d_out, int out_size)
{
    const float* x     = (const float*)d_in[0];
    const float* adj   = (const float*)d_in[1];
    const float* gcn_w = (const float*)d_in[2];
    const float* gcn_b = (const float*)d_in[3];
    const float* fc_w  = (const float*)d_in[4];
    const float* fc_b  = (const float*)d_in[5];
    float* out = (float*)d_out;

    __half *gwT_h, *x_h, *adj_h, *fcw_h, *supT_h, *mid_h;
    float* partial;
    cudaGetSymbolAddress((void**)&gwT_h,  g_gwT_h);
    cudaGetSymbolAddress((void**)&x_h,    g_x_h);
    cudaGetSymbolAddress((void**)&adj_h,  g_adj_h);
    cudaGetSymbolAddress((void**)&fcw_h,  g_fcw_h);
    cudaGetSymbolAddress((void**)&supT_h, g_supT_h);
    cudaGetSymbolAddress((void**)&mid_h,  g_mid_h);
    cudaGetSymbolAddress((void**)&partial, g_partial);

    cudaFuncSetAttribute(gemm_s<1>, cudaFuncAttributeMaxDynamicSharedMemorySize, SMEM2);
    cudaFuncSetAttribute(gemm_s<2>, cudaFuncAttributeMaxDynamicSharedMemorySize, SMEM2);
    cudaFuncSetAttribute(gemm_s<3>, cudaFuncAttributeMaxDynamicSharedMemorySize, SMEM2);

    // 0) preps
    prep_wh<<<NFEAT, NFEAT>>>(gcn_w, gwT_h);
    {
        long n4 = (long)BATCH * NODES * NFEAT / 4;
        conv_h<<<(unsigned)((n4 + 255) / 256), 256>>>(x, x_h, n4);
    }
    {
        long n4 = (long)BATCH * NODES * NODES / 4;
        conv_h<<<(unsigned)((n4 + 255) / 256), 256>>>(adj, adj_h, n4);
    }
    {
        long n4 = (long)NFEAT * KTOT / 4;
        conv_h<<<(unsigned)((n4 + 255) / 256), 256>>>(fc_w, fcw_h, n4);
    }

    // 1) supT[b][g][node] = sum_f gwT[g][f] * x_b[node][f]
    {
        dim3 grid(BATCH, 2);
        gemm_s<1><<<grid, 256, SMEM2>>>(
            gwT_h, x_h, NFEAT, NFEAT, nullptr, nullptr, supT_h, 4);
    }
    // 2) mid[b][node][g] = sum_k adj_b[node][k]*supT_b[g][k] + gcn_b[g]
    {
        dim3 grid(BATCH, 2);
        gemm_s<2><<<grid, 256, SMEM2>>>(
            adj_h, supT_h, NODES, NODES, gcn_b, nullptr, mid_h, 2);
    }
    // 3) partial[s][m][n] = sum_{k in slice} mid[m][k]*fcw[n][k]
    {
        dim3 grid(SPLITS, BATCH / 128, 2);
        gemm_s<3><<<grid, 256, SMEM2>>>(
            mid_h, fcw_h, KTOT, KTOT, nullptr, partial, nullptr, KSLICE / 64);
    }
    // 4) reduce + bias + output sections
    finalize<<<SEC / 256, 256>>>(partial, fc_b, x, out);
}

// round 11
// speedup vs baseline: 2.1921x; 1.0212x over previous
#include <cuda_runtime.h>
#include <cuda_fp16.h>
#include <cstdint>

#define BATCH 512
#define NODES 128
#define NFEAT 256
#define KTOT  32768          // NODES*NFEAT
#define SPLITS 32
#define KSLICE 1024          // KTOT/SPLITS
#define SEC   (BATCH*NFEAT)  // 131072

// ---------------------------------------------------------------------------
// Scratch (__device__ globals; allocation is forbidden)
// ---------------------------------------------------------------------------
__device__ __half g_gwT_h[NFEAT * NFEAT];                    // [g][f]
__device__ __half g_x_h[(size_t)BATCH * NODES * NFEAT];      // [b][node][f]
__device__ __half g_adj_h[(size_t)BATCH * NODES * NODES];    // [b][n][m]
__device__ __half g_fcw_h[(size_t)NFEAT * KTOT];             // [o][k]
__device__ __half g_supT_h[(size_t)BATCH * NFEAT * NODES];   // [b][g][node]
__device__ __half g_mid_h[(size_t)BATCH * NODES * NFEAT];    // [b][node][g]
__device__ float  g_partial[(size_t)SPLITS * BATCH * NFEAT];

// ---------------------------------------------------------------------------
#define SW128(o) ((o) ^ (((o) >> 3) & 0x70))

__device__ __forceinline__ uint32_t smem_u32(const void* p) {
    uint32_t a;
    asm("{ .reg .u64 t; cvta.to.shared.u64 t, %1; cvt.u32.u64 %0, t; }"
        : "=r"(a) : "l"(p));
    return a;
}
__device__ __forceinline__ uint32_t pack2h(__half a, __half b) {
    __half2 t = __halves2half2(a, b);
    return *reinterpret_cast<uint32_t*>(&t);
}

// ---------------------------------------------------------------------------
// cp.async (base PTX, sm_80+)
// ---------------------------------------------------------------------------
__device__ __forceinline__ void cpa16(uint32_t s, const void* g) {
    asm volatile("cp.async.cg.shared.global [%0], [%1], 16;" :: "r"(s), "l"(g));
}
#define CP_COMMIT()  asm volatile("cp.async.commit_group;" ::: "memory")
#define CP_WAIT1()   asm volatile("cp.async.wait_group 1;" ::: "memory")
#define CP_WAIT0()   asm volatile("cp.async.wait_group 0;" ::: "memory")

// ---------------------------------------------------------------------------
// warp-MMA primitives (base PTX)
// ---------------------------------------------------------------------------
__device__ __forceinline__ void ldsm_x4(uint32_t addr, uint32_t* r) {
    asm volatile("ldmatrix.sync.aligned.m8n8.x4.shared.b16 {%0,%1,%2,%3}, [%4];"
        : "=r"(r[0]), "=r"(r[1]), "=r"(r[2]), "=r"(r[3]) : "r"(addr));
}
__device__ __forceinline__ void mma_f16(float* c, const uint32_t* a, const uint32_t* b) {
    asm volatile(
        "mma.sync.aligned.m16n8k16.row.col.f32.f16.f16.f32 "
        "{%0,%1,%2,%3}, {%4,%5,%6,%7}, {%8,%9}, {%0,%1,%2,%3};"
        : "+f"(c[0]), "+f"(c[1]), "+f"(c[2]), "+f"(c[3])
        : "r"(a[0]), "r"(a[1]), "r"(a[2]), "r"(a[3]), "r"(b[0]), "r"(b[1]));
}
// A frags, m64: 4 x ldsm_x4
__device__ __forceinline__ void load_afrags(uint32_t tbase, int m0w, int kb,
                                            int lane, uint32_t* a) {
    const int kpart = ((lane >> 4) << 4);
    #pragma unroll
    for (int i = 0; i < 4; i++) {
        int row = m0w + 16 * i + (lane & 15);
        ldsm_x4(tbase + SW128(row * 128 + kb + kpart), a + 4 * i);
    }
}
// B frags, n32 (4 n8-tiles) in 2 ldsm_x4; tile j at b + 4*(j>>1) + 2*(j&1)
__device__ __forceinline__ void load_b32(uint32_t tbase, int n0, int kb,
                                         int lane, uint32_t* b) {
    const int kpart = (((lane >> 3) & 1) << 4);
    const int tofs  = ((lane >> 4) & 1) * 8;
    int row = n0 + tofs + (lane & 7);
    ldsm_x4(tbase + SW128(row * 128 + kb + kpart),        b);
    ldsm_x4(tbase + SW128((row + 16) * 128 + kb + kpart), b + 4);
}
#define BJ(b, j) ((b) + 4 * ((j) >> 1) + 2 * ((j) & 1))

// ---------------------------------------------------------------------------
// Single-fp16 GEMM: C[128,128] = A[128,K] * B[128,K]^T, 1 MMA per k16.
// CTA 128x128, warp 64x32, 256 threads, 2-stage pipeline, occupancy 2.
//  MODE 1: A=gwT, B=x_b     -> supT fp16          (ldc=NODES)   [persistent]
//  MODE 2: A=adj_b, B=supT  -> mid fp16 + bias    (ldc=NFEAT)   [persistent]
//  MODE 3: A=mid, B=fcw     -> partial fp32       (ldc=NFEAT)   [1 wave grid]
// Stage: A 16KB | B 16KB = 32KB.
// ---------------------------------------------------------------------------
#define OFF_B 16384
#define STG   32768
#define SMEM2 (2 * STG + 1024)   // 66560 B; 2 CTAs/SM = 133KB

template <int MODE>
__global__ void __launch_bounds__(256, 2)
gemm_s(const __half* __restrict__ Abase, const __half* __restrict__ Bbase,
       long sA, long sB,
       const float* __restrict__ biasBase,
       float* __restrict__ outFbase, __half* __restrict__ outHbase,
       int nkt, int njobs)
{
    extern __shared__ char smraw[];
    char* sm = (char*)(((uintptr_t)smraw + 1023) & ~(uintptr_t)1023);
    const uint32_t sb = smem_u32(sm);

    const int tid  = threadIdx.x;
    const int lane = tid & 31;
    const int w    = tid >> 5;
    const int m0w  = (w >> 2) * 64;
    const int n0w  = (w & 3) * 32;

    const int job0  = (MODE == 3) ? 0 : blockIdx.x;
    const int jstep = (MODE == 3) ? 1 : gridDim.x;
    const int jend  = (MODE == 3) ? 1 : njobs;

    for (int job = job0; job < jend; job += jstep) {
        const __half* A = Abase;
        const __half* B = Bbase;
        const float* bias = biasBase;
        float* outF = outFbase;
        __half* outH = outHbase;
        int ldc = 0, coloff = 0;
        long outOfs = 0;

        if constexpr (MODE == 1) {
            long b = job >> 1, mh = job & 1;
            A += mh * 128 * NFEAT;                    // gwT rows
            B += b * (long)(NODES * NFEAT);           // x_b
            outOfs = b * (long)(NFEAT * NODES) + mh * 128 * NODES;
            ldc = NODES;
        } else if constexpr (MODE == 2) {
            long b = job >> 1, nh = job & 1;
            A += b * (long)(NODES * NODES);           // adj_b
            B += b * (long)(NFEAT * NODES) + nh * 128 * NODES;   // supT rows
            outOfs = b * (long)(NODES * NFEAT);
            bias += nh * 128;
            ldc = NFEAT; coloff = (int)nh * 128;
        } else {
            long split = blockIdx.x, mb = blockIdx.y, nh = blockIdx.z;
            A += (mb * 128) * (long)KTOT + split * KSLICE;       // mid
            B += (nh * 128) * (long)KTOT + split * KSLICE;       // fcw
            outF += split * (long)SEC + (mb * 128) * (long)NFEAT + nh * 128;
            ldc = NFEAT;
        }

        // stage arrays: [0]=A, [OFF_B]=B; each 128 rows x 128B
        auto stage_load = [&](int stage, int kt) {
            const uint32_t base = sb + stage * STG;
            const int k0 = kt * 64;
            #pragma unroll
            for (int it = 0; it < 4; it++) {
                int idx = tid + it * 256;
                int row = idx >> 3, c = idx & 7;
                uint32_t so = SW128(row * 128 + c * 16);
                cpa16(base + so,         A + (long)row * sA + k0 + c * 8);
                cpa16(base + OFF_B + so, B + (long)row * sB + k0 + c * 8);
            }
        };

        float acc[64];
        #pragma unroll
        for (int i = 0; i < 64; i++) acc[i] = 0.f;

        __syncthreads();   // protect stages from previous job's readers
        stage_load(0, 0); CP_COMMIT();
        if (nkt > 1) stage_load(1, 1);
        CP_COMMIT();

        for (int kt = 0; kt < nkt; kt++) {
            const int st = kt & 1;
            if (kt + 1 < nkt) CP_WAIT1(); else CP_WAIT0();
            __syncthreads();

            const uint32_t base = sb + st * STG;
            #pragma unroll
            for (int ks = 0; ks < 4; ks++) {
                const int kb = ks * 32;
                uint32_t ah[16], b1[8];
                load_afrags(base,      m0w, kb, lane, ah);
                load_b32(base + OFF_B, n0w, kb, lane, b1);
                #pragma unroll
                for (int i = 0; i < 4; i++)
                    #pragma unroll
                    for (int j = 0; j < 4; j++)
                        mma_f16(acc + (i * 4 + j) * 4, ah + 4 * i, BJ(b1, j));
            }
            __syncthreads();
            if (kt + 2 < nkt) { stage_load(st, kt + 2); }
            CP_COMMIT();
        }

        // ---- epilogue ----
        #pragma unroll
        for (int i = 0; i < 4; i++) {
            #pragma unroll
            for (int j = 0; j < 4; j++) {
                const float* c = acc + (i * 4 + j) * 4;
                int r0 = m0w + 16 * i + (lane >> 2);
                int c0 = n0w + 8 * j + 2 * (lane & 3);
                if constexpr (MODE == 3) {
                    *(float2*)&outF[(long)r0 * ldc + c0]       = make_float2(c[0], c[1]);
                    *(float2*)&outF[(long)(r0 + 8) * ldc + c0] = make_float2(c[2], c[3]);
                } else {
                    float v0 = c[0], v1 = c[1], v2 = c[2], v3 = c[3];
                    if constexpr (MODE == 2) {
                        float b0 = __ldg(&bias[c0]), b1 = __ldg(&bias[c0 + 1]);
                        v0 += b0; v1 += b1; v2 += b0; v3 += b1;
                    }
                    long o0 = outOfs + (long)r0 * ldc + coloff + c0;
                    long o1 = outOfs + (long)(r0 + 8) * ldc + coloff + c0;
                    *(uint32_t*)&outH[o0] = pack2h(__float2half_rn(v0), __float2half_rn(v1));
                    *(uint32_t*)&outH[o1] = pack2h(__float2half_rn(v2), __float2half_rn(v3));
                }
            }
        }
    }
}

// ---------------------------------------------------------------------------
// prep: fused fp32 -> fp16 conversion for three arrays in one launch
// ---------------------------------------------------------------------------
__global__ void __launch_bounds__(256)
conv3(const float* __restrict__ s0, __half* __restrict__ d0, long n0,
      const float* __restrict__ s1, __half* __restrict__ d1, long n1,
      const float* __restrict__ s2, __half* __restrict__ d2, long n2)
{
    long i = (long)blockIdx.x * 256 + threadIdx.x;
    const float* s; __half* d; long off;
    if (i < n0)            { s = s0; d = d0; off = i; }
    else if (i < n0 + n1)  { s = s1; d = d1; off = i - n0; }
    else if (i < n0 + n1 + n2) { s = s2; d = d2; off = i - n0 - n1; }
    else return;
    float4 v = ((const float4*)s)[off];
    ((uint2*)d)[off] = make_uint2(
        pack2h(__float2half_rn(v.x), __float2half_rn(v.y)),
        pack2h(__float2half_rn(v.z), __float2half_rn(v.w)));
}

// gcn_w transpose -> single fp16
__global__ void __launch_bounds__(256)
prep_wh(const float* __restrict__ wsrc, __half* __restrict__ dst)
{
    int g = blockIdx.x, f = threadIdx.x;
    dst[(long)g * NFEAT + f] = __float2half_rn(wsrc[(long)f * NFEAT + g]);
}

// ---------------------------------------------------------------------------
// finalize: reduce split-K partials + fc_b, write 3 output sections
// ---------------------------------------------------------------------------
__global__ void __launch_bounds__(256)
finalize(const float* __restrict__ P, const float* __restrict__ fc_b,
         const float* __restrict__ x, float* __restrict__ out)
{
    const int idx = blockIdx.x * blockDim.x + threadIdx.x;
    if (idx >= SEC) return;
    const int b = idx >> 8;
    const int f = idx & 255;
    float v = fc_b[f];
    #pragma unroll
    for (int s = 0; s < SPLITS; s++)
        v += P[(long)s * SEC + idx];
    out[idx]           = v;
    out[2 * SEC + idx] = v;
    out[SEC + idx]     = x[(long)b * KTOT + f];   // x[b,0,f]
}

// ---------------------------------------------------------------------------
extern "C" void kernel_launch(void* const* d_in, const int* in_sizes, int n_in,
                              void* d_out, int out_size)
{
    const float* x     = (const float*)d_in[0];
    const float* adj   = (const float*)d_in[1];
    const float* gcn_w = (const float*)d_in[2];
    const float* gcn_b = (const float*)d_in[3];
    const float* fc_w  = (const float*)d_in[4];
    const float* fc_b  = (const float*)d_in[5];
    float* out = (float*)d_out;

    __half *gwT_h, *x_h, *adj_h, *fcw_h, *supT_h, *mid_h;
    float* partial;
    cudaGetSymbolAddress((void**)&gwT_h,  g_gwT_h);
    cudaGetSymbolAddress((void**)&x_h,    g_x_h);
    cudaGetSymbolAddress((void**)&adj_h,  g_adj_h);
    cudaGetSymbolAddress((void**)&fcw_h,  g_fcw_h);
    cudaGetSymbolAddress((void**)&supT_h, g_supT_h);
    cudaGetSymbolAddress((void**)&mid_h,  g_mid_h);
    cudaGetSymbolAddress((void**)&partial, g_partial);

    cudaFuncSetAttribute(gemm_s<1>, cudaFuncAttributeMaxDynamicSharedMemorySize, SMEM2);
    cudaFuncSetAttribute(gemm_s<2>, cudaFuncAttributeMaxDynamicSharedMemorySize, SMEM2);
    cudaFuncSetAttribute(gemm_s<3>, cudaFuncAttributeMaxDynamicSharedMemorySize, SMEM2);

    int nsm = 148;
    cudaDeviceGetAttribute(&nsm, cudaDevAttrMultiProcessorCount, 0);
    const int pgrid = 2 * nsm;    // occ-2 persistent grid

    // 0) fused preps: x, adj, fc_w -> fp16 (one launch)
    {
        long n0 = (long)BATCH * NODES * NFEAT / 4;    // x
        long n1 = (long)BATCH * NODES * NODES / 4;    // adj
        long n2 = (long)NFEAT * KTOT / 4;             // fc_w
        long tot = n0 + n1 + n2;
        conv3<<<(unsigned)((tot + 255) / 256), 256>>>(
            x, x_h, n0, adj, adj_h, n1, fc_w, fcw_h, n2);
    }
    prep_wh<<<NFEAT, NFEAT>>>(gcn_w, gwT_h);

    // 1) supT[b][g][node] = sum_f gwT[g][f] * x_b[node][f]   (persistent)
    gemm_s<1><<<pgrid, 256, SMEM2>>>(
        gwT_h, x_h, NFEAT, NFEAT, nullptr, nullptr, supT_h, 4, BATCH * 2);

    // 2) mid[b][node][g] = sum_k adj_b[node][k]*supT_b[g][k] + gcn_b[g]  (persistent)
    gemm_s<2><<<pgrid, 256, SMEM2>>>(
        adj_h, supT_h, NODES, NODES, gcn_b, nullptr, mid_h, 2, BATCH * 2);

    // 3) partial[s][m][n] = sum_{k in slice} mid[m][k]*fcw[n][k]  (single wave)
    {
        dim3 grid(SPLITS, BATCH / 128, 2);
        gemm_s<3><<<grid, 256, SMEM2>>>(
            mid_h, fcw_h, KTOT, KTOT, nullptr, partial, nullptr, KSLICE / 64, 1);
    }
    // 4) reduce + bias + output sections
    finalize<<<SEC / 256, 256>>>(partial, fc_b, x, out);
}